// round 15
// baseline (speedup 1.0000x reference)
#include <cuda_runtime.h>
#include <cuda_bf16.h>
#include <cuda_fp16.h>
#include <math.h>
#include <cstdint>

// ---------------------------------------------------------------------------
// SimpleGPT forward. R15: logits GEMM single-product fp16 (D = y16 @ W16,
// fp32 acc). Error budget (calibrated): sqrt(rho_y^2 + rho_W^2) ~ 3e-4.
// FFN/attn/qkv from R13/R14 (validated).
// B=64 T=50 V=32000 E=64 DH=128 H=8 M=256
// ---------------------------------------------------------------------------
constexpr int B   = 64;
constexpr int T   = 50;
constexpr int NV  = 32000;
constexpr int E   = 64;
constexpr int DH  = 128;
constexpr int H   = 8;
constexpr int FM  = 256;
constexpr int BT  = B * T;
constexpr int OD  = H * DH;

typedef unsigned long long u64;

__device__ __forceinline__ u64 ffma2(u64 a, u64 b, u64 c) {
    u64 d;
    asm("fma.rn.f32x2 %0, %1, %2, %3;" : "=l"(d) : "l"(a), "l"(b), "l"(c));
    return d;
}
__device__ __forceinline__ u64 bcast2(float x) {
    u64 d;
    unsigned xi = __float_as_uint(x);
    asm("mov.b64 %0, {%1, %1};" : "=l"(d) : "r"(xi));
    return d;
}
__device__ __forceinline__ u64 pack2f(float x, float y) {
    u64 d;
    unsigned xi = __float_as_uint(x), yi = __float_as_uint(y);
    asm("mov.b64 %0, {%1, %2};" : "=l"(d) : "r"(xi), "r"(yi));
    return d;
}
__device__ __forceinline__ u64 pk(uint32_t lo, uint32_t hi) {
    u64 d;
    asm("mov.b64 %0, {%1, %2};" : "=l"(d) : "r"(lo), "r"(hi));
    return d;
}
__device__ __forceinline__ float2 unpack2(u64 v) {
    unsigned lo, hi;
    asm("mov.b64 {%0, %1}, %2;" : "=r"(lo), "=r"(hi) : "l"(v));
    return make_float2(__uint_as_float(lo), __uint_as_float(hi));
}
__device__ __forceinline__ uint32_t smem_u32(const void* p) {
    uint32_t a;
    asm("{ .reg .u64 t; cvta.to.shared.u64 t, %1; cvt.u32.u64 %0, t; }" : "=r"(a) : "l"(p));
    return a;
}
__device__ __forceinline__ void cpa16(uint32_t saddr, const void* gptr) {
    asm volatile("cp.async.cg.shared.global [%0], [%1], 16;"
                 :: "r"(saddr), "l"(__cvta_generic_to_global(gptr)) : "memory");
}
#define CPA_COMMIT() asm volatile("cp.async.commit_group;" ::: "memory")
#define CPA_WAIT1()  asm volatile("cp.async.wait_group 1;" ::: "memory")
#define SW128(x) ((x) ^ (((x) >> 3) & 0x70))

__device__ __forceinline__ float gelu_exact(float x) {
    return 0.5f * x * (1.0f + erff(x * 0.70710678118654752f));
}
__device__ __forceinline__ void split2(float v0, float v1,
                                       __nv_bfloat162& hh, __nv_bfloat162& ll) {
    __nv_bfloat16 h0 = __float2bfloat16_rn(v0);
    __nv_bfloat16 h1 = __float2bfloat16_rn(v1);
    hh.x = h0; hh.y = h1;
    ll.x = __float2bfloat16_rn(v0 - __bfloat162float(h0));
    ll.y = __float2bfloat16_rn(v1 - __bfloat162float(h1));
}

// Scratch (device globals — referenced ONLY from device code)
__device__ __align__(16) float g_q[B * H * T * DH];
__device__ __align__(16) float g_k[B * H * T * DH];
__device__ __align__(16) float g_v[B * H * T * DH];
__device__ __align__(16) __nv_bfloat16 g_oh[BT * OD];
__device__ __align__(16) __nv_bfloat16 g_ol[BT * OD];
__device__ __align__(16) __nv_bfloat16 g_ah[BT * E];
__device__ __align__(16) __nv_bfloat16 g_al[BT * E];
__device__ __align__(16) __half g_yh[BT * E];              // fp16 y
__device__ __align__(16) __half g_wh[(size_t)NV * E];      // fp16 Wf^T [n][k]
__device__ __align__(16) __nv_bfloat16 g_woTh[OD * E];
__device__ __align__(16) __nv_bfloat16 g_woTl[OD * E];
__device__ __align__(16) __nv_bfloat16 g_w1Th[FM * E];
__device__ __align__(16) __nv_bfloat16 g_w1Tl[FM * E];
__device__ __align__(16) __nv_bfloat16 g_w2Th[E * FM];
__device__ __align__(16) __nv_bfloat16 g_w2Tl[E * FM];

// ---------------------------------------------------------------------------
// 0a) Wf -> transposed fp16
// ---------------------------------------------------------------------------
__global__ void k_cvt_wf(const float* __restrict__ Wf) {
    __shared__ float s[64 * 65];
    int tid = threadIdx.x;
    int nb = blockIdx.x * 64;
#pragma unroll
    for (int it = 0; it < 16; it++) {
        int i = tid + it * 256;
        int k = i >> 6, j = i & 63;
        s[k * 65 + j] = Wf[(size_t)k * NV + nb + j];
    }
    __syncthreads();
#pragma unroll
    for (int it = 0; it < 8; it++) {
        int i = tid + it * 256;
        int n = i >> 5, k2 = (i & 31) * 2;
        __half2 hh;
        hh.x = __float2half_rn(s[k2 * 65 + n]);
        hh.y = __float2half_rn(s[(k2 + 1) * 65 + n]);
        *(__half2*)(g_wh + (size_t)(nb + n) * 64 + k2) = hh;
    }
}

// ---------------------------------------------------------------------------
// 0b) Transpose+split in[R][C] fp32 -> [C][R] bf16 hi/lo (device-selected out)
// ---------------------------------------------------------------------------
__global__ void k_cvt_t(const float* __restrict__ in, int R, int C, int which) {
    __shared__ float s[64 * 65];
    int tid = threadIdx.x;
    int cb = blockIdx.x * 64, rb = blockIdx.y * 64;

    __nv_bfloat16* oh;
    __nv_bfloat16* ol;
    if (which == 0)      { oh = g_woTh; ol = g_woTl; }
    else if (which == 1) { oh = g_w1Th; ol = g_w1Tl; }
    else                 { oh = g_w2Th; ol = g_w2Tl; }

#pragma unroll
    for (int it = 0; it < 16; it++) {
        int i = tid + it * 256;
        int r = i >> 6, c = i & 63;
        s[r * 65 + c] = in[(size_t)(rb + r) * C + cb + c];
    }
    __syncthreads();
#pragma unroll
    for (int it = 0; it < 8; it++) {
        int i = tid + it * 256;
        int n = i >> 5, k2 = (i & 31) * 2;
        __nv_bfloat162 hh, ll;
        split2(s[k2 * 65 + n], s[(k2 + 1) * 65 + n], hh, ll);
        size_t o = (size_t)(cb + n) * R + rb + k2;
        *(__nv_bfloat162*)(oh + o) = hh;
        *(__nv_bfloat162*)(ol + o) = ll;
    }
}

// ---------------------------------------------------------------------------
// 1) QKV (+ fused embedding)
// ---------------------------------------------------------------------------
__global__ void k_qkv(const int* __restrict__ x,
                      const float* __restrict__ te, const float* __restrict__ pe,
                      const float* __restrict__ Wq, const float* __restrict__ bq,
                      const float* __restrict__ Wk, const float* __restrict__ bk,
                      const float* __restrict__ Wv, const float* __restrict__ bv) {
    __shared__ __align__(16) float h_s[T * E];
    int b = blockIdx.x, h = blockIdx.y, m = blockIdx.z;
    int d = threadIdx.x;

    for (int i = d; i < T * E; i += 128) {
        int t = i >> 6;
        h_s[i] = te[x[b * T + t] * E + (i & 63)] + pe[i];
    }

    const float* W    = (m == 0) ? Wq : ((m == 1) ? Wk : Wv);
    const float* bias = (m == 0) ? bq : ((m == 1) ? bk : bv);
    float* out = ((m == 0) ? g_q : ((m == 1) ? g_k : g_v)) + ((size_t)(b * H + h) * T) * DH;

    u64 wp[32];
#pragma unroll
    for (int e2 = 0; e2 < 32; e2++)
        wp[e2] = pack2f(W[(h * E + 2 * e2) * DH + d], W[(h * E + 2 * e2 + 1) * DH + d]);
    float bb = bias[h * DH + d];
    __syncthreads();

    for (int t = 0; t < T; t++) {
        u64 a0 = 0ull, a1 = 0ull;
        const u64* hp = (const u64*)(h_s + t * E);
#pragma unroll
        for (int e2 = 0; e2 < 32; e2 += 2) {
            a0 = ffma2(wp[e2],     hp[e2],     a0);
            a1 = ffma2(wp[e2 + 1], hp[e2 + 1], a1);
        }
        float2 s0 = unpack2(a0), s1 = unpack2(a1);
        out[t * DH + d] = s0.x + s0.y + s1.x + s1.y + bb;
    }
}

// ---------------------------------------------------------------------------
// 2) Attention (R6 core; epilogue emits bf16 hi/lo o)
// ---------------------------------------------------------------------------
constexpr int KP132 = 132;
constexpr int A_KOFF = T * KP132;
constexpr int A_VOFF = A_KOFF + T * DH;
constexpr int A_QOFF = A_VOFF;
constexpr int A_POFF = A_QOFF + 8 * 8 * DH;
constexpr int A_TOTF = A_POFF + 8 * 8 * 64;

__global__ void __launch_bounds__(256)
k_attn() {
    extern __shared__ float sm[];
    float* K_s = sm;
    float* V_s = sm + A_KOFF;
    float* q_s = sm + A_QOFF;
    float* p_s = sm + A_POFF;

    int b = blockIdx.x, h = blockIdx.y;
    int tid = threadIdx.x, w = tid >> 5, lane = tid & 31;
    size_t base = ((size_t)(b * H + h) * T) * DH;

    for (int i = tid; i < T * 32; i += 256) {
        int s = i >> 5, c4 = (i & 31) * 4;
        *(float4*)(K_s + s * KP132 + c4) = *(const float4*)(g_k + base + s * DH + c4);
        *(float4*)(V_s + s * DH + c4)    = *(const float4*)(g_v + base + s * DH + c4);
    }
    __syncthreads();

#pragma unroll
    for (int j = 0; j < 7; j++) {
        int t = w + 8 * j;
        if (t < T)
            *(float4*)(q_s + (w * 8 + j) * DH + lane * 4) =
                *(const float4*)(g_q + base + (size_t)t * DH + lane * 4);
    }
    __syncwarp();

    int s0 = lane, s1 = lane + 32;
    const float* k0p = K_s + s0 * KP132;
    const float* k1p = K_s + s1 * KP132;

    u64 acc[7][2];
#pragma unroll
    for (int j = 0; j < 7; j++) { acc[j][0] = 0ull; acc[j][1] = 0ull; }

#pragma unroll 8
    for (int c = 0; c < DH; c += 4) {
        uint4 k0 = *(const uint4*)(k0p + c);
        uint4 k1 = *(const uint4*)(k1p + c);
        u64 k0a = pk(k0.x, k0.y), k0b = pk(k0.z, k0.w);
        u64 k1a = pk(k1.x, k1.y), k1b = pk(k1.z, k1.w);
#pragma unroll
        for (int j = 0; j < 7; j++) {
            uint4 qv = *(const uint4*)(q_s + (w * 8 + j) * DH + c);
            u64 qa = pk(qv.x, qv.y), qb = pk(qv.z, qv.w);
            acc[j][0] = ffma2(qb, k0b, ffma2(qa, k0a, acc[j][0]));
            acc[j][1] = ffma2(qb, k1b, ffma2(qa, k1a, acc[j][1]));
        }
    }

    const float scale = 0.0883883476483184f;
    float sum[7], inv[7];
#pragma unroll
    for (int j = 0; j < 7; j++) {
        int t = w + 8 * j;
        bool valid = t < T;
        float2 f0 = unpack2(acc[j][0]);
        float2 f1 = unpack2(acc[j][1]);
        float sc0 = (f0.x + f0.y) * scale;
        float sc1 = (f1.x + f1.y) * scale;
        float e0 = (valid && s0 <= t) ? __expf(sc0) : 0.f;
        float e1 = (valid && s1 <= t) ? __expf(sc1) : 0.f;
        p_s[(w * 8 + j) * 64 + s0] = e0;
        p_s[(w * 8 + j) * 64 + s1] = e1;
        sum[j] = e0 + e1;
    }
#pragma unroll
    for (int off = 16; off; off >>= 1) {
#pragma unroll
        for (int j = 0; j < 7; j++)
            sum[j] += __shfl_xor_sync(0xffffffffu, sum[j], off);
    }
#pragma unroll
    for (int j = 0; j < 7; j++) inv[j] = 1.0f / sum[j];
    __syncwarp();

    u64 av[7][2];
#pragma unroll
    for (int j = 0; j < 7; j++) { av[j][0] = 0ull; av[j][1] = 0ull; }

    const float* vb = V_s + lane * 4;
    const float* pb = p_s + w * 8 * 64;
#pragma unroll 2
    for (int s = 0; s < T; s++) {
        uint4 vv = *(const uint4*)(vb + s * DH);
        u64 v01 = pk(vv.x, vv.y), v23 = pk(vv.z, vv.w);
#pragma unroll
        for (int j = 0; j < 7; j++) {
            u64 pj = bcast2(pb[j * 64 + s]);
            av[j][0] = ffma2(pj, v01, av[j][0]);
            av[j][1] = ffma2(pj, v23, av[j][1]);
        }
    }

#pragma unroll
    for (int j = 0; j < 7; j++) {
        int t = w + 8 * j;
        if (t < T) {
            float2 o01 = unpack2(av[j][0]), o23 = unpack2(av[j][1]);
            __nv_bfloat162 hA, lA, hB, lB;
            split2(o01.x * inv[j], o01.y * inv[j], hA, lA);
            split2(o23.x * inv[j], o23.y * inv[j], hB, lB);
            size_t o = (size_t)(b * T + t) * OD + h * DH + lane * 4;
            *(__nv_bfloat162*)(g_oh + o)     = hA;
            *(__nv_bfloat162*)(g_oh + o + 2) = hB;
            *(__nv_bfloat162*)(g_ol + o)     = lA;
            *(__nv_bfloat162*)(g_ol + o + 2) = lB;
        }
    }
}

// ---------------------------------------------------------------------------
// mma.sync helpers
// ---------------------------------------------------------------------------
__device__ __forceinline__ void ldm4(uint32_t& r0, uint32_t& r1,
                                     uint32_t& r2, uint32_t& r3, uint32_t addr) {
    asm volatile("ldmatrix.sync.aligned.m8n8.x4.shared.b16 {%0,%1,%2,%3}, [%4];"
                 : "=r"(r0), "=r"(r1), "=r"(r2), "=r"(r3) : "r"(addr));
}
__device__ __forceinline__ void mma16816(float* c, const uint32_t* a,
                                         uint32_t b0, uint32_t b1) {
    asm volatile(
        "mma.sync.aligned.m16n8k16.row.col.f32.bf16.bf16.f32 "
        "{%0,%1,%2,%3}, {%4,%5,%6,%7}, {%8,%9}, {%0,%1,%2,%3};"
        : "+f"(c[0]), "+f"(c[1]), "+f"(c[2]), "+f"(c[3])
        : "r"(a[0]), "r"(a[1]), "r"(a[2]), "r"(a[3]), "r"(b0), "r"(b1));
}
__device__ __forceinline__ void mma16816h(float* c, const uint32_t* a,
                                          uint32_t b0, uint32_t b1) {
    asm volatile(
        "mma.sync.aligned.m16n8k16.row.col.f32.f16.f16.f32 "
        "{%0,%1,%2,%3}, {%4,%5,%6,%7}, {%8,%9}, {%0,%1,%2,%3};"
        : "+f"(c[0]), "+f"(c[1]), "+f"(c[2]), "+f"(c[3])
        : "r"(a[0]), "r"(a[1]), "r"(a[2]), "r"(a[3]), "r"(b0), "r"(b1));
}

// ---------------------------------------------------------------------------
// 3a) FFN stage A: a = o @ Wo + bo -> bf16 hi/lo (R13, validated)
// ---------------------------------------------------------------------------
__global__ void __launch_bounds__(256)
k_ffn_a(const float* __restrict__ bo) {
    __shared__ __align__(16) char smem[24576];
    uint32_t sb = smem_u32(smem);
    int tid = threadIdx.x, wid = tid >> 5, lane = tid & 31;
    int rb = blockIdx.x * 32;
    int wm = wid & 1;
    int wn = wid >> 1;

    int g = lane >> 2, q4 = lane & 3;
    int a_row  = wm * 16 + (lane & 15);
    int a_colb = (lane >> 4) * 16;
    int b_n    = wn * 16 + ((lane >> 3) >> 1) * 8 + (lane & 7);
    int b_kb   = ((lane >> 3) & 1) * 16;

    float cA[2][4];
#pragma unroll
    for (int q = 0; q < 2; q++)
#pragma unroll
        for (int j = 0; j < 4; j++) cA[q][j] = 0.f;

    for (int kc = 0; kc < 16; kc++) {
        for (int i = tid; i < 512; i += 256) {
            int half = i >> 8, r = (i >> 3) & 31, c = i & 7;
            uint32_t sw = SW128((uint32_t)(r * 128 + c * 16));
            const __nv_bfloat16* src =
                (half ? g_ol : g_oh) + (size_t)(rb + r) * OD + kc * 64 + c * 8;
            *(uint4*)(smem + half * 4096 + sw) = *(const uint4*)src;
        }
        for (int i = tid; i < 1024; i += 256) {
            int half = i >> 9, n = (i >> 3) & 63, c = i & 7;
            uint32_t sw = SW128((uint32_t)(n * 128 + c * 16));
            const __nv_bfloat16* src =
                (half ? g_woTl : g_woTh) + (size_t)n * OD + kc * 64 + c * 8;
            *(uint4*)(smem + 8192 + half * 8192 + sw) = *(const uint4*)src;
        }
        __syncthreads();

        uint32_t Ah = sb, Al = sb + 4096, Bh = sb + 8192, Bl = sb + 16384;
#pragma unroll
        for (int ks = 0; ks < 4; ks++) {
            uint32_t swa = SW128((uint32_t)(a_row * 128 + a_colb + ks * 32));
            uint32_t swb = SW128((uint32_t)(b_n * 128 + b_kb + ks * 32));
            uint32_t ah[4], al[4], bh[4], bl[4];
            ldm4(ah[0], ah[1], ah[2], ah[3], Ah + swa);
            ldm4(al[0], al[1], al[2], al[3], Al + swa);
            ldm4(bh[0], bh[1], bh[2], bh[3], Bh + swb);
            ldm4(bl[0], bl[1], bl[2], bl[3], Bl + swb);
#pragma unroll
            for (int q = 0; q < 2; q++) {
                mma16816(cA[q], ah, bh[2 * q], bh[2 * q + 1]);
                mma16816(cA[q], ah, bl[2 * q], bl[2 * q + 1]);
                mma16816(cA[q], al, bh[2 * q], bh[2 * q + 1]);
            }
        }
        __syncthreads();
    }

#pragma unroll
    for (int q = 0; q < 2; q++) {
        int col = wn * 16 + q * 8 + 2 * q4;
        float b0 = bo[col], b1v = bo[col + 1];
        int r0 = rb + wm * 16 + g, r1 = r0 + 8;
        __nv_bfloat162 hh0, ll0, hh1, ll1;
        split2(cA[q][0] + b0, cA[q][1] + b1v, hh0, ll0);
        split2(cA[q][2] + b0, cA[q][3] + b1v, hh1, ll1);
        *(__nv_bfloat162*)(g_ah + r0 * 64 + col) = hh0;
        *(__nv_bfloat162*)(g_al + r0 * 64 + col) = ll0;
        *(__nv_bfloat162*)(g_ah + r1 * 64 + col) = hh1;
        *(__nv_bfloat162*)(g_al + r1 * 64 + col) = ll1;
    }
}

// ---------------------------------------------------------------------------
// 3b) FFN stage B+C (R13 structure; epilogue emits single fp16 y)
// ---------------------------------------------------------------------------
constexpr int FB_W = 0;
constexpr int FB_A = 32768;
constexpr int FB_M = 40960;
constexpr int FB_TOT = 73728;

__global__ void __launch_bounds__(256)
k_ffn_b(const float* __restrict__ b1, const float* __restrict__ b2) {
    extern __shared__ char smem[];
    uint32_t sb = smem_u32(smem);
    int tid = threadIdx.x, wid = tid >> 5, lane = tid & 31;
    int rb = blockIdx.x * 32;
    int wm = wid & 1;
    int wn = wid >> 1;

    int g = lane >> 2, q4 = lane & 3;
    int a_row  = wm * 16 + (lane & 15);
    int a_colb = (lane >> 4) * 16;
    int bn_sub = ((lane >> 3) >> 1) * 8 + (lane & 7);
    int b_kb   = ((lane >> 3) & 1) * 16;

    for (int i = tid; i < 512; i += 256) {
        int half = i >> 8, r = (i >> 3) & 31, c = i & 7;
        uint32_t sw = SW128((uint32_t)(r * 128 + c * 16));
        const __nv_bfloat16* src =
            (half ? g_al : g_ah) + (size_t)(rb + r) * 64 + c * 8;
        *(uint4*)(smem + FB_A + half * 4096 + sw) = *(const uint4*)src;
    }

    for (int half = 0; half < 2; half++) {
        for (int i = tid; i < 2048; i += 256) {
            int hl = i >> 10;
            int idx = i & 1023;
            int nl = idx >> 3, c = idx & 7;
            uint32_t sw = SW128((uint32_t)(nl * 128 + c * 16));
            const __nv_bfloat16* src = (hl ? g_w1Tl : g_w1Th)
                + (size_t)(half * 128 + nl) * 64 + c * 8;
            *(uint4*)(smem + FB_W + hl * 16384 + sw) = *(const uint4*)src;
        }
        __syncthreads();

        float c2f[4][4];
#pragma unroll
        for (int i = 0; i < 4; i++)
#pragma unroll
            for (int j = 0; j < 4; j++) c2f[i][j] = 0.f;

        uint32_t Ah = sb + FB_A, Al = Ah + 4096;
        uint32_t Bh = sb + FB_W, Bl = Bh + 16384;
#pragma unroll
        for (int ks = 0; ks < 4; ks++) {
            uint32_t swa = SW128((uint32_t)(a_row * 128 + a_colb + ks * 32));
            uint32_t ah[4], al[4];
            ldm4(ah[0], ah[1], ah[2], ah[3], Ah + swa);
            ldm4(al[0], al[1], al[2], al[3], Al + swa);
#pragma unroll
            for (int nb2 = 0; nb2 < 2; nb2++) {
                int rowl = wn * 32 + nb2 * 16 + bn_sub;
                uint32_t swb = SW128((uint32_t)(rowl * 128 + b_kb + ks * 32));
                uint32_t bh[4], bl[4];
                ldm4(bh[0], bh[1], bh[2], bh[3], Bh + swb);
                ldm4(bl[0], bl[1], bl[2], bl[3], Bl + swb);
#pragma unroll
                for (int q = 0; q < 2; q++) {
                    mma16816(c2f[2 * nb2 + q], ah, bh[2 * q], bh[2 * q + 1]);
                    mma16816(c2f[2 * nb2 + q], ah, bl[2 * q], bl[2 * q + 1]);
                    mma16816(c2f[2 * nb2 + q], al, bh[2 * q], bh[2 * q + 1]);
                }
            }
        }

#pragma unroll
        for (int nb2 = 0; nb2 < 2; nb2++) {
#pragma unroll
            for (int q = 0; q < 2; q++) {
                int col = half * 128 + wn * 32 + nb2 * 16 + q * 8 + 2 * q4;
                float bj0 = b1[col], bj1 = b1[col + 1];
                int chunk = col >> 6, k2 = col & 63;
                const float* cf = c2f[2 * nb2 + q];
                __nv_bfloat162 hh0, ll0, hh1, ll1;
                split2(gelu_exact(cf[0] + bj0), gelu_exact(cf[1] + bj1), hh0, ll0);
                split2(gelu_exact(cf[2] + bj0), gelu_exact(cf[3] + bj1), hh1, ll1);
                uint32_t coff = (uint32_t)(FB_M + chunk * 8192);
                uint32_t sw0 = SW128((uint32_t)((wm * 16 + g) * 128 + k2 * 2));
                uint32_t sw1 = SW128((uint32_t)((wm * 16 + g + 8) * 128 + k2 * 2));
                *(__nv_bfloat162*)(smem + coff + sw0)        = hh0;
                *(__nv_bfloat162*)(smem + coff + 4096 + sw0) = ll0;
                *(__nv_bfloat162*)(smem + coff + sw1)        = hh1;
                *(__nv_bfloat162*)(smem + coff + 4096 + sw1) = ll1;
            }
        }
        __syncthreads();
    }

    float cC[2][4];
#pragma unroll
    for (int q = 0; q < 2; q++)
#pragma unroll
        for (int j = 0; j < 4; j++) cC[q][j] = 0.f;

    int b_n = wn * 16 + bn_sub;
    for (int pair = 0; pair < 2; pair++) {
        for (int i = tid; i < 2048; i += 256) {
            int cl = i >> 10;
            int rest = i & 1023;
            int hl = rest >> 9;
            int idx = rest & 511;
            int n = idx >> 3, c = idx & 7;
            uint32_t sw = SW128((uint32_t)(n * 128 + c * 16));
            const __nv_bfloat16* src = (hl ? g_w2Tl : g_w2Th)
                + (size_t)n * FM + (2 * pair + cl) * 64 + c * 8;
            *(uint4*)(smem + FB_W + cl * 16384 + hl * 8192 + sw) = *(const uint4*)src;
        }
        __syncthreads();

#pragma unroll
        for (int cl = 0; cl < 2; cl++) {
            int chunk = 2 * pair + cl;
            uint32_t Ah = sb + FB_M + chunk * 8192, Al = Ah + 4096;
            uint32_t Bh = sb + FB_W + cl * 16384,   Bl = Bh + 8192;
#pragma unroll
            for (int ks = 0; ks < 4; ks++) {
                uint32_t swa = SW128((uint32_t)(a_row * 128 + a_colb + ks * 32));
                uint32_t swb = SW128((uint32_t)(b_n * 128 + b_kb + ks * 32));
                uint32_t ah[4], al[4], bh[4], bl[4];
                ldm4(ah[0], ah[1], ah[2], ah[3], Ah + swa);
                ldm4(al[0], al[1], al[2], al[3], Al + swa);
                ldm4(bh[0], bh[1], bh[2], bh[3], Bh + swb);
                ldm4(bl[0], bl[1], bl[2], bl[3], Bl + swb);
#pragma unroll
                for (int q = 0; q < 2; q++) {
                    mma16816(cC[q], ah, bh[2 * q], bh[2 * q + 1]);
                    mma16816(cC[q], ah, bl[2 * q], bl[2 * q + 1]);
                    mma16816(cC[q], al, bh[2 * q], bh[2 * q + 1]);
                }
            }
        }
        __syncthreads();
    }

    // epilogue: +b2 -> single fp16 y
#pragma unroll
    for (int q = 0; q < 2; q++) {
        int col = wn * 16 + q * 8 + 2 * q4;
        float b20 = b2[col], b21 = b2[col + 1];
        int r0 = rb + wm * 16 + g, r1 = r0 + 8;
        __half2 hh0, hh1;
        hh0.x = __float2half_rn(cC[q][0] + b20);
        hh0.y = __float2half_rn(cC[q][1] + b21);
        hh1.x = __float2half_rn(cC[q][2] + b20);
        hh1.y = __float2half_rn(cC[q][3] + b21);
        *(__half2*)(g_yh + r0 * 64 + col) = hh0;
        *(__half2*)(g_yh + r1 * 64 + col) = hh1;
    }
}

// ---------------------------------------------------------------------------
// 4) Logits GEMM, single-product fp16: D = y16 @ W16 + bf (fp32 acc).
//    Persistent column-stripe; Wh resident 16KB; A dbuf 2x8KB. 32KB smem.
// ---------------------------------------------------------------------------
constexpr int S_BH = 0;          // 16384
constexpr int S_A  = 16384;      // 2 x 8192
constexpr int S_TOT = 32768;

__global__ void __launch_bounds__(256, 2)
k_logits_mma(const float* __restrict__ bf, float* __restrict__ out) {
    extern __shared__ char smem[];
    uint32_t sb = smem_u32(smem);
    int tid = threadIdx.x, wid = tid >> 5, lane = tid & 31;
    int nb = blockIdx.x * 128;
    int wm = wid & 1;
    int wn = wid >> 1;

    for (int idx = tid; idx < 1024; idx += 256) {
        int r = idx >> 3, c = idx & 7;
        uint32_t sw = SW128((uint32_t)(r * 128 + c * 16));
        *(uint4*)(smem + S_BH + sw) =
            *(const uint4*)(g_wh + (size_t)(nb + r) * 64 + c * 8);
    }

    int g = lane >> 2, q4 = lane & 3;
    float2 bias_r[4];
#pragma unroll
    for (int nbk = 0; nbk < 4; nbk++)
        bias_r[nbk] = *(const float2*)(bf + nb + wn * 32 + nbk * 8 + 2 * q4);

    // prefetch A tile 0 (64 rows x 64 fp16 = 8KB)
    {
        uint32_t ab = sb + S_A;
        for (int idx = tid; idx < 512; idx += 256) {
            int r = idx >> 3, c = idx & 7;
            uint32_t sw = SW128((uint32_t)(r * 128 + c * 16));
            cpa16(ab + sw, g_yh + (size_t)r * 64 + c * 8);
        }
    }
    CPA_COMMIT();
    __syncthreads();

    int a_row  = wm * 32 + (lane & 15);
    int a_colb = (lane >> 4) * 16;
    int b_n    = wn * 32 + ((lane >> 3) >> 1) * 8 + (lane & 7);
    int b_kb   = ((lane >> 3) & 1) * 16;

    for (int it = 0; it < 50; it++) {
        int p = it & 1;
        if (it + 1 < 50) {
            uint32_t ab = sb + S_A + (1 - p) * 8192;
            for (int idx = tid; idx < 512; idx += 256) {
                int r = idx >> 3, c = idx & 7;
                uint32_t sw = SW128((uint32_t)(r * 128 + c * 16));
                cpa16(ab + sw, g_yh + (size_t)((it + 1) * 64 + r) * 64 + c * 8);
            }
        }
        CPA_COMMIT();
        CPA_WAIT1();
        __syncthreads();

        float c[2][4][4];
#pragma unroll
        for (int mb = 0; mb < 2; mb++)
#pragma unroll
            for (int nbk = 0; nbk < 4; nbk++)
#pragma unroll
                for (int j = 0; j < 4; j++) c[mb][nbk][j] = 0.f;

        uint32_t Ah = sb + S_A + p * 8192;
        uint32_t Bh = sb + S_BH;

#pragma unroll
        for (int ks = 0; ks < 4; ks++) {
            uint32_t swa0 = SW128((uint32_t)(a_row * 128 + a_colb + ks * 32));
            uint32_t swa1 = SW128((uint32_t)((a_row + 16) * 128 + a_colb + ks * 32));
            uint32_t swb0 = SW128((uint32_t)(b_n * 128 + b_kb + ks * 32));
            uint32_t swb1 = SW128((uint32_t)((b_n + 16) * 128 + b_kb + ks * 32));

            uint32_t ah0[4], ah1[4], bh[8];
            ldm4(ah0[0], ah0[1], ah0[2], ah0[3], Ah + swa0);
            ldm4(ah1[0], ah1[1], ah1[2], ah1[3], Ah + swa1);
            ldm4(bh[0], bh[1], bh[2], bh[3], Bh + swb0);
            ldm4(bh[4], bh[5], bh[6], bh[7], Bh + swb1);

#pragma unroll
            for (int q = 0; q < 2; q++) {
                mma16816h(c[0][2 * q],     ah0, bh[4 * q],     bh[4 * q + 1]);
                mma16816h(c[0][2 * q + 1], ah0, bh[4 * q + 2], bh[4 * q + 3]);
                mma16816h(c[1][2 * q],     ah1, bh[4 * q],     bh[4 * q + 1]);
                mma16816h(c[1][2 * q + 1], ah1, bh[4 * q + 2], bh[4 * q + 3]);
            }
        }

#pragma unroll
        for (int mb = 0; mb < 2; mb++) {
            int row = it * 64 + wm * 32 + mb * 16 + g;
            float* orow = out + (size_t)row * NV;
#pragma unroll
            for (int nbk = 0; nbk < 4; nbk++) {
                int col = nb + wn * 32 + nbk * 8 + 2 * q4;
                float2 bv = bias_r[nbk];
                float2 v0 = make_float2(c[mb][nbk][0] + bv.x, c[mb][nbk][1] + bv.y);
                float2 v1 = make_float2(c[mb][nbk][2] + bv.x, c[mb][nbk][3] + bv.y);
                *(float2*)(orow + col)          = v0;
                *(float2*)(orow + 8 * NV + col) = v1;
            }
        }
        __syncthreads();
    }
}

// ---------------------------------------------------------------------------
extern "C" void kernel_launch(void* const* d_in, const int* in_sizes, int n_in,
                              void* d_out, int out_size) {
    (void)in_sizes; (void)n_in; (void)out_size;
    const int*   x  = (const int*)d_in[0];
    const float* te = (const float*)d_in[1];
    const float* pe = (const float*)d_in[2];
    const float* Wq = (const float*)d_in[3];  const float* bq = (const float*)d_in[4];
    const float* Wk = (const float*)d_in[5];  const float* bk = (const float*)d_in[6];
    const float* Wv = (const float*)d_in[7];  const float* bv = (const float*)d_in[8];
    const float* Wo = (const float*)d_in[9];  const float* bo = (const float*)d_in[10];
    const float* W1 = (const float*)d_in[11]; const float* b1 = (const float*)d_in[12];
    const float* W2 = (const float*)d_in[13]; const float* b2 = (const float*)d_in[14];
    const float* Wf = (const float*)d_in[15]; const float* bf = (const float*)d_in[16];
    float* out = (float*)d_out;

    k_cvt_wf<<<NV / 64, 256>>>(Wf);
    k_cvt_t<<<dim3(1, 16), 256>>>(Wo, OD, E, 0);
    k_cvt_t<<<dim3(4, 1), 256>>>(W1, E, FM, 1);
    k_cvt_t<<<dim3(1, 4), 256>>>(W2, FM, E, 2);
    k_qkv<<<dim3(B, H, 3), 128>>>(x, te, pe, Wq, bq, Wk, bk, Wv, bv);

    int attn_smem = A_TOTF * (int)sizeof(float);
    cudaFuncSetAttribute(k_attn, cudaFuncAttributeMaxDynamicSharedMemorySize, attn_smem);
    k_attn<<<dim3(B, H), 256, attn_smem>>>();

    k_ffn_a<<<BT / 32, 256>>>(bo);

    cudaFuncSetAttribute(k_ffn_b, cudaFuncAttributeMaxDynamicSharedMemorySize, FB_TOT);
    k_ffn_b<<<BT / 32, 256, FB_TOT>>>(b1, b2);

    cudaFuncSetAttribute(k_logits_mma, cudaFuncAttributeMaxDynamicSharedMemorySize, S_TOT);
    k_logits_mma<<<NV / 128, 256, S_TOT>>>(bf, out);
}

// round 16
// speedup vs baseline: 1.4007x; 1.4007x over previous
#include <cuda_runtime.h>
#include <cuda_bf16.h>
#include <cuda_fp16.h>
#include <math.h>
#include <cstdint>

// ---------------------------------------------------------------------------
// SimpleGPT forward. R16: revert to R14 config (fp16 2-product logits:
// D = yh@Wh + (yl*1024)@Wh/1024 — measured 274.5us, rel_err 2.1e-4).
// New: all weight-conversion kernels merged into ONE launch (k_cvt_all).
// B=64 T=50 V=32000 E=64 DH=128 H=8 M=256
// ---------------------------------------------------------------------------
constexpr int B   = 64;
constexpr int T   = 50;
constexpr int NV  = 32000;
constexpr int E   = 64;
constexpr int DH  = 128;
constexpr int H   = 8;
constexpr int FM  = 256;
constexpr int BT  = B * T;
constexpr int OD  = H * DH;

typedef unsigned long long u64;

__device__ __forceinline__ u64 ffma2(u64 a, u64 b, u64 c) {
    u64 d;
    asm("fma.rn.f32x2 %0, %1, %2, %3;" : "=l"(d) : "l"(a), "l"(b), "l"(c));
    return d;
}
__device__ __forceinline__ u64 bcast2(float x) {
    u64 d;
    unsigned xi = __float_as_uint(x);
    asm("mov.b64 %0, {%1, %1};" : "=l"(d) : "r"(xi));
    return d;
}
__device__ __forceinline__ u64 pack2f(float x, float y) {
    u64 d;
    unsigned xi = __float_as_uint(x), yi = __float_as_uint(y);
    asm("mov.b64 %0, {%1, %2};" : "=l"(d) : "r"(xi), "r"(yi));
    return d;
}
__device__ __forceinline__ u64 pk(uint32_t lo, uint32_t hi) {
    u64 d;
    asm("mov.b64 %0, {%1, %2};" : "=l"(d) : "r"(lo), "r"(hi));
    return d;
}
__device__ __forceinline__ float2 unpack2(u64 v) {
    unsigned lo, hi;
    asm("mov.b64 {%0, %1}, %2;" : "=r"(lo), "=r"(hi) : "l"(v));
    return make_float2(__uint_as_float(lo), __uint_as_float(hi));
}
__device__ __forceinline__ uint32_t smem_u32(const void* p) {
    uint32_t a;
    asm("{ .reg .u64 t; cvta.to.shared.u64 t, %1; cvt.u32.u64 %0, t; }" : "=r"(a) : "l"(p));
    return a;
}
__device__ __forceinline__ void cpa16(uint32_t saddr, const void* gptr) {
    asm volatile("cp.async.cg.shared.global [%0], [%1], 16;"
                 :: "r"(saddr), "l"(__cvta_generic_to_global(gptr)) : "memory");
}
#define CPA_COMMIT() asm volatile("cp.async.commit_group;" ::: "memory")
#define CPA_WAIT1()  asm volatile("cp.async.wait_group 1;" ::: "memory")
#define SW128(x) ((x) ^ (((x) >> 3) & 0x70))

__device__ __forceinline__ float gelu_exact(float x) {
    return 0.5f * x * (1.0f + erff(x * 0.70710678118654752f));
}
__device__ __forceinline__ void split2(float v0, float v1,
                                       __nv_bfloat162& hh, __nv_bfloat162& ll) {
    __nv_bfloat16 h0 = __float2bfloat16_rn(v0);
    __nv_bfloat16 h1 = __float2bfloat16_rn(v1);
    hh.x = h0; hh.y = h1;
    ll.x = __float2bfloat16_rn(v0 - __bfloat162float(h0));
    ll.y = __float2bfloat16_rn(v1 - __bfloat162float(h1));
}

// Scratch (device globals — referenced ONLY from device code)
__device__ __align__(16) float g_q[B * H * T * DH];
__device__ __align__(16) float g_k[B * H * T * DH];
__device__ __align__(16) float g_v[B * H * T * DH];
__device__ __align__(16) __nv_bfloat16 g_oh[BT * OD];
__device__ __align__(16) __nv_bfloat16 g_ol[BT * OD];
__device__ __align__(16) __nv_bfloat16 g_ah[BT * E];
__device__ __align__(16) __nv_bfloat16 g_al[BT * E];
__device__ __align__(16) __half g_yh[BT * E];              // fp16 y hi
__device__ __align__(16) __half g_yl[BT * E];              // fp16 (y-yh)*1024
__device__ __align__(16) __half g_wh[(size_t)NV * E];      // fp16 Wf^T [n][k]
__device__ __align__(16) __nv_bfloat16 g_woTh[OD * E];
__device__ __align__(16) __nv_bfloat16 g_woTl[OD * E];
__device__ __align__(16) __nv_bfloat16 g_w1Th[FM * E];
__device__ __align__(16) __nv_bfloat16 g_w1Tl[FM * E];
__device__ __align__(16) __nv_bfloat16 g_w2Th[E * FM];
__device__ __align__(16) __nv_bfloat16 g_w2Tl[E * FM];

// ---------------------------------------------------------------------------
// 0) ALL weight conversions in one launch. Blocks 0..499: Wf -> g_wh (fp16,
//    transposed). Blocks 500..523: Wo/W1/W2 -> bf16 hi/lo transposed.
// ---------------------------------------------------------------------------
__global__ void k_cvt_all(const float* __restrict__ Wf,
                          const float* __restrict__ Wo,
                          const float* __restrict__ W1,
                          const float* __restrict__ W2) {
    __shared__ float s[64 * 65];
    int tid = threadIdx.x;
    int bid = blockIdx.x;

    if (bid < 500) {
        int nb = bid * 64;
#pragma unroll
        for (int it = 0; it < 16; it++) {
            int i = tid + it * 256;
            int k = i >> 6, j = i & 63;
            s[k * 65 + j] = Wf[(size_t)k * NV + nb + j];
        }
        __syncthreads();
#pragma unroll
        for (int it = 0; it < 8; it++) {
            int i = tid + it * 256;
            int n = i >> 5, k2 = (i & 31) * 2;
            __half2 hh;
            hh.x = __float2half_rn(s[k2 * 65 + n]);
            hh.y = __float2half_rn(s[(k2 + 1) * 65 + n]);
            *(__half2*)(g_wh + (size_t)(nb + n) * 64 + k2) = hh;
        }
        return;
    }

    int r = bid - 500;   // 0..23
    const float* in;
    __nv_bfloat16 *oh, *ol;
    int R, C, cb, rb;
    if (r < 16)      { in = Wo; oh = g_woTh; ol = g_woTl; R = OD; C = E;  cb = 0;      rb = r * 64; }
    else if (r < 20) { in = W1; oh = g_w1Th; ol = g_w1Tl; R = E;  C = FM; cb = (r - 16) * 64; rb = 0; }
    else             { in = W2; oh = g_w2Th; ol = g_w2Tl; R = FM; C = E;  cb = 0;      rb = (r - 20) * 64; }

#pragma unroll
    for (int it = 0; it < 16; it++) {
        int i = tid + it * 256;
        int rr = i >> 6, c = i & 63;
        s[rr * 65 + c] = in[(size_t)(rb + rr) * C + cb + c];
    }
    __syncthreads();
#pragma unroll
    for (int it = 0; it < 8; it++) {
        int i = tid + it * 256;
        int n = i >> 5, k2 = (i & 31) * 2;
        __nv_bfloat162 hh, ll;
        split2(s[k2 * 65 + n], s[(k2 + 1) * 65 + n], hh, ll);
        size_t o = (size_t)(cb + n) * R + rb + k2;
        *(__nv_bfloat162*)(oh + o) = hh;
        *(__nv_bfloat162*)(ol + o) = ll;
    }
}

// ---------------------------------------------------------------------------
// 1) QKV (+ fused embedding)
// ---------------------------------------------------------------------------
__global__ void k_qkv(const int* __restrict__ x,
                      const float* __restrict__ te, const float* __restrict__ pe,
                      const float* __restrict__ Wq, const float* __restrict__ bq,
                      const float* __restrict__ Wk, const float* __restrict__ bk,
                      const float* __restrict__ Wv, const float* __restrict__ bv) {
    __shared__ __align__(16) float h_s[T * E];
    int b = blockIdx.x, h = blockIdx.y, m = blockIdx.z;
    int d = threadIdx.x;

    for (int i = d; i < T * E; i += 128) {
        int t = i >> 6;
        h_s[i] = te[x[b * T + t] * E + (i & 63)] + pe[i];
    }

    const float* W    = (m == 0) ? Wq : ((m == 1) ? Wk : Wv);
    const float* bias = (m == 0) ? bq : ((m == 1) ? bk : bv);
    float* out = ((m == 0) ? g_q : ((m == 1) ? g_k : g_v)) + ((size_t)(b * H + h) * T) * DH;

    u64 wp[32];
#pragma unroll
    for (int e2 = 0; e2 < 32; e2++)
        wp[e2] = pack2f(W[(h * E + 2 * e2) * DH + d], W[(h * E + 2 * e2 + 1) * DH + d]);
    float bb = bias[h * DH + d];
    __syncthreads();

    for (int t = 0; t < T; t++) {
        u64 a0 = 0ull, a1 = 0ull;
        const u64* hp = (const u64*)(h_s + t * E);
#pragma unroll
        for (int e2 = 0; e2 < 32; e2 += 2) {
            a0 = ffma2(wp[e2],     hp[e2],     a0);
            a1 = ffma2(wp[e2 + 1], hp[e2 + 1], a1);
        }
        float2 s0 = unpack2(a0), s1 = unpack2(a1);
        out[t * DH + d] = s0.x + s0.y + s1.x + s1.y + bb;
    }
}

// ---------------------------------------------------------------------------
// 2) Attention (R6 core; epilogue emits bf16 hi/lo o)
// ---------------------------------------------------------------------------
constexpr int KP132 = 132;
constexpr int A_KOFF = T * KP132;
constexpr int A_VOFF = A_KOFF + T * DH;
constexpr int A_QOFF = A_VOFF;
constexpr int A_POFF = A_QOFF + 8 * 8 * DH;
constexpr int A_TOTF = A_POFF + 8 * 8 * 64;

__global__ void __launch_bounds__(256)
k_attn() {
    extern __shared__ float sm[];
    float* K_s = sm;
    float* V_s = sm + A_KOFF;
    float* q_s = sm + A_QOFF;
    float* p_s = sm + A_POFF;

    int b = blockIdx.x, h = blockIdx.y;
    int tid = threadIdx.x, w = tid >> 5, lane = tid & 31;
    size_t base = ((size_t)(b * H + h) * T) * DH;

    for (int i = tid; i < T * 32; i += 256) {
        int s = i >> 5, c4 = (i & 31) * 4;
        *(float4*)(K_s + s * KP132 + c4) = *(const float4*)(g_k + base + s * DH + c4);
        *(float4*)(V_s + s * DH + c4)    = *(const float4*)(g_v + base + s * DH + c4);
    }
    __syncthreads();

#pragma unroll
    for (int j = 0; j < 7; j++) {
        int t = w + 8 * j;
        if (t < T)
            *(float4*)(q_s + (w * 8 + j) * DH + lane * 4) =
                *(const float4*)(g_q + base + (size_t)t * DH + lane * 4);
    }
    __syncwarp();

    int s0 = lane, s1 = lane + 32;
    const float* k0p = K_s + s0 * KP132;
    const float* k1p = K_s + s1 * KP132;

    u64 acc[7][2];
#pragma unroll
    for (int j = 0; j < 7; j++) { acc[j][0] = 0ull; acc[j][1] = 0ull; }

#pragma unroll 8
    for (int c = 0; c < DH; c += 4) {
        uint4 k0 = *(const uint4*)(k0p + c);
        uint4 k1 = *(const uint4*)(k1p + c);
        u64 k0a = pk(k0.x, k0.y), k0b = pk(k0.z, k0.w);
        u64 k1a = pk(k1.x, k1.y), k1b = pk(k1.z, k1.w);
#pragma unroll
        for (int j = 0; j < 7; j++) {
            uint4 qv = *(const uint4*)(q_s + (w * 8 + j) * DH + c);
            u64 qa = pk(qv.x, qv.y), qb = pk(qv.z, qv.w);
            acc[j][0] = ffma2(qb, k0b, ffma2(qa, k0a, acc[j][0]));
            acc[j][1] = ffma2(qb, k1b, ffma2(qa, k1a, acc[j][1]));
        }
    }

    const float scale = 0.0883883476483184f;
    float sum[7], inv[7];
#pragma unroll
    for (int j = 0; j < 7; j++) {
        int t = w + 8 * j;
        bool valid = t < T;
        float2 f0 = unpack2(acc[j][0]);
        float2 f1 = unpack2(acc[j][1]);
        float sc0 = (f0.x + f0.y) * scale;
        float sc1 = (f1.x + f1.y) * scale;
        float e0 = (valid && s0 <= t) ? __expf(sc0) : 0.f;
        float e1 = (valid && s1 <= t) ? __expf(sc1) : 0.f;
        p_s[(w * 8 + j) * 64 + s0] = e0;
        p_s[(w * 8 + j) * 64 + s1] = e1;
        sum[j] = e0 + e1;
    }
#pragma unroll
    for (int off = 16; off; off >>= 1) {
#pragma unroll
        for (int j = 0; j < 7; j++)
            sum[j] += __shfl_xor_sync(0xffffffffu, sum[j], off);
    }
#pragma unroll
    for (int j = 0; j < 7; j++) inv[j] = 1.0f / sum[j];
    __syncwarp();

    u64 av[7][2];
#pragma unroll
    for (int j = 0; j < 7; j++) { av[j][0] = 0ull; av[j][1] = 0ull; }

    const float* vb = V_s + lane * 4;
    const float* pb = p_s + w * 8 * 64;
#pragma unroll 2
    for (int s = 0; s < T; s++) {
        uint4 vv = *(const uint4*)(vb + s * DH);
        u64 v01 = pk(vv.x, vv.y), v23 = pk(vv.z, vv.w);
#pragma unroll
        for (int j = 0; j < 7; j++) {
            u64 pj = bcast2(pb[j * 64 + s]);
            av[j][0] = ffma2(pj, v01, av[j][0]);
            av[j][1] = ffma2(pj, v23, av[j][1]);
        }
    }

#pragma unroll
    for (int j = 0; j < 7; j++) {
        int t = w + 8 * j;
        if (t < T) {
            float2 o01 = unpack2(av[j][0]), o23 = unpack2(av[j][1]);
            __nv_bfloat162 hA, lA, hB, lB;
            split2(o01.x * inv[j], o01.y * inv[j], hA, lA);
            split2(o23.x * inv[j], o23.y * inv[j], hB, lB);
            size_t o = (size_t)(b * T + t) * OD + h * DH + lane * 4;
            *(__nv_bfloat162*)(g_oh + o)     = hA;
            *(__nv_bfloat162*)(g_oh + o + 2) = hB;
            *(__nv_bfloat162*)(g_ol + o)     = lA;
            *(__nv_bfloat162*)(g_ol + o + 2) = lB;
        }
    }
}

// ---------------------------------------------------------------------------
// mma.sync helpers
// ---------------------------------------------------------------------------
__device__ __forceinline__ void ldm4(uint32_t& r0, uint32_t& r1,
                                     uint32_t& r2, uint32_t& r3, uint32_t addr) {
    asm volatile("ldmatrix.sync.aligned.m8n8.x4.shared.b16 {%0,%1,%2,%3}, [%4];"
                 : "=r"(r0), "=r"(r1), "=r"(r2), "=r"(r3) : "r"(addr));
}
__device__ __forceinline__ void mma16816(float* c, const uint32_t* a,
                                         uint32_t b0, uint32_t b1) {
    asm volatile(
        "mma.sync.aligned.m16n8k16.row.col.f32.bf16.bf16.f32 "
        "{%0,%1,%2,%3}, {%4,%5,%6,%7}, {%8,%9}, {%0,%1,%2,%3};"
        : "+f"(c[0]), "+f"(c[1]), "+f"(c[2]), "+f"(c[3])
        : "r"(a[0]), "r"(a[1]), "r"(a[2]), "r"(a[3]), "r"(b0), "r"(b1));
}
__device__ __forceinline__ void mma16816h(float* c, const uint32_t* a,
                                          uint32_t b0, uint32_t b1) {
    asm volatile(
        "mma.sync.aligned.m16n8k16.row.col.f32.f16.f16.f32 "
        "{%0,%1,%2,%3}, {%4,%5,%6,%7}, {%8,%9}, {%0,%1,%2,%3};"
        : "+f"(c[0]), "+f"(c[1]), "+f"(c[2]), "+f"(c[3])
        : "r"(a[0]), "r"(a[1]), "r"(a[2]), "r"(a[3]), "r"(b0), "r"(b1));
}

// ---------------------------------------------------------------------------
// 3a) FFN stage A: a = o @ Wo + bo -> bf16 hi/lo (R13, validated)
// ---------------------------------------------------------------------------
__global__ void __launch_bounds__(256)
k_ffn_a(const float* __restrict__ bo) {
    __shared__ __align__(16) char smem[24576];
    uint32_t sb = smem_u32(smem);
    int tid = threadIdx.x, wid = tid >> 5, lane = tid & 31;
    int rb = blockIdx.x * 32;
    int wm = wid & 1;
    int wn = wid >> 1;

    int g = lane >> 2, q4 = lane & 3;
    int a_row  = wm * 16 + (lane & 15);
    int a_colb = (lane >> 4) * 16;
    int b_n    = wn * 16 + ((lane >> 3) >> 1) * 8 + (lane & 7);
    int b_kb   = ((lane >> 3) & 1) * 16;

    float cA[2][4];
#pragma unroll
    for (int q = 0; q < 2; q++)
#pragma unroll
        for (int j = 0; j < 4; j++) cA[q][j] = 0.f;

    for (int kc = 0; kc < 16; kc++) {
        for (int i = tid; i < 512; i += 256) {
            int half = i >> 8, r = (i >> 3) & 31, c = i & 7;
            uint32_t sw = SW128((uint32_t)(r * 128 + c * 16));
            const __nv_bfloat16* src =
                (half ? g_ol : g_oh) + (size_t)(rb + r) * OD + kc * 64 + c * 8;
            *(uint4*)(smem + half * 4096 + sw) = *(const uint4*)src;
        }
        for (int i = tid; i < 1024; i += 256) {
            int half = i >> 9, n = (i >> 3) & 63, c = i & 7;
            uint32_t sw = SW128((uint32_t)(n * 128 + c * 16));
            const __nv_bfloat16* src =
                (half ? g_woTl : g_woTh) + (size_t)n * OD + kc * 64 + c * 8;
            *(uint4*)(smem + 8192 + half * 8192 + sw) = *(const uint4*)src;
        }
        __syncthreads();

        uint32_t Ah = sb, Al = sb + 4096, Bh = sb + 8192, Bl = sb + 16384;
#pragma unroll
        for (int ks = 0; ks < 4; ks++) {
            uint32_t swa = SW128((uint32_t)(a_row * 128 + a_colb + ks * 32));
            uint32_t swb = SW128((uint32_t)(b_n * 128 + b_kb + ks * 32));
            uint32_t ah[4], al[4], bh[4], bl[4];
            ldm4(ah[0], ah[1], ah[2], ah[3], Ah + swa);
            ldm4(al[0], al[1], al[2], al[3], Al + swa);
            ldm4(bh[0], bh[1], bh[2], bh[3], Bh + swb);
            ldm4(bl[0], bl[1], bl[2], bl[3], Bl + swb);
#pragma unroll
            for (int q = 0; q < 2; q++) {
                mma16816(cA[q], ah, bh[2 * q], bh[2 * q + 1]);
                mma16816(cA[q], ah, bl[2 * q], bl[2 * q + 1]);
                mma16816(cA[q], al, bh[2 * q], bh[2 * q + 1]);
            }
        }
        __syncthreads();
    }

#pragma unroll
    for (int q = 0; q < 2; q++) {
        int col = wn * 16 + q * 8 + 2 * q4;
        float b0 = bo[col], b1v = bo[col + 1];
        int r0 = rb + wm * 16 + g, r1 = r0 + 8;
        __nv_bfloat162 hh0, ll0, hh1, ll1;
        split2(cA[q][0] + b0, cA[q][1] + b1v, hh0, ll0);
        split2(cA[q][2] + b0, cA[q][3] + b1v, hh1, ll1);
        *(__nv_bfloat162*)(g_ah + r0 * 64 + col) = hh0;
        *(__nv_bfloat162*)(g_al + r0 * 64 + col) = ll0;
        *(__nv_bfloat162*)(g_ah + r1 * 64 + col) = hh1;
        *(__nv_bfloat162*)(g_al + r1 * 64 + col) = ll1;
    }
}

// ---------------------------------------------------------------------------
// 3b) FFN stage B+C (R13 structure; epilogue emits fp16 y splits, yl x1024)
// ---------------------------------------------------------------------------
constexpr int FB_W = 0;
constexpr int FB_A = 32768;
constexpr int FB_M = 40960;
constexpr int FB_TOT = 73728;

__global__ void __launch_bounds__(256)
k_ffn_b(const float* __restrict__ b1, const float* __restrict__ b2) {
    extern __shared__ char smem[];
    uint32_t sb = smem_u32(smem);
    int tid = threadIdx.x, wid = tid >> 5, lane = tid & 31;
    int rb = blockIdx.x * 32;
    int wm = wid & 1;
    int wn = wid >> 1;

    int g = lane >> 2, q4 = lane & 3;
    int a_row  = wm * 16 + (lane & 15);
    int a_colb = (lane >> 4) * 16;
    int bn_sub = ((lane >> 3) >> 1) * 8 + (lane & 7);
    int b_kb   = ((lane >> 3) & 1) * 16;

    for (int i = tid; i < 512; i += 256) {
        int half = i >> 8, r = (i >> 3) & 31, c = i & 7;
        uint32_t sw = SW128((uint32_t)(r * 128 + c * 16));
        const __nv_bfloat16* src =
            (half ? g_al : g_ah) + (size_t)(rb + r) * 64 + c * 8;
        *(uint4*)(smem + FB_A + half * 4096 + sw) = *(const uint4*)src;
    }

    for (int half = 0; half < 2; half++) {
        for (int i = tid; i < 2048; i += 256) {
            int hl = i >> 10;
            int idx = i & 1023;
            int nl = idx >> 3, c = idx & 7;
            uint32_t sw = SW128((uint32_t)(nl * 128 + c * 16));
            const __nv_bfloat16* src = (hl ? g_w1Tl : g_w1Th)
                + (size_t)(half * 128 + nl) * 64 + c * 8;
            *(uint4*)(smem + FB_W + hl * 16384 + sw) = *(const uint4*)src;
        }
        __syncthreads();

        float c2f[4][4];
#pragma unroll
        for (int i = 0; i < 4; i++)
#pragma unroll
            for (int j = 0; j < 4; j++) c2f[i][j] = 0.f;

        uint32_t Ah = sb + FB_A, Al = Ah + 4096;
        uint32_t Bh = sb + FB_W, Bl = Bh + 16384;
#pragma unroll
        for (int ks = 0; ks < 4; ks++) {
            uint32_t swa = SW128((uint32_t)(a_row * 128 + a_colb + ks * 32));
            uint32_t ah[4], al[4];
            ldm4(ah[0], ah[1], ah[2], ah[3], Ah + swa);
            ldm4(al[0], al[1], al[2], al[3], Al + swa);
#pragma unroll
            for (int nb2 = 0; nb2 < 2; nb2++) {
                int rowl = wn * 32 + nb2 * 16 + bn_sub;
                uint32_t swb = SW128((uint32_t)(rowl * 128 + b_kb + ks * 32));
                uint32_t bh[4], bl[4];
                ldm4(bh[0], bh[1], bh[2], bh[3], Bh + swb);
                ldm4(bl[0], bl[1], bl[2], bl[3], Bl + swb);
#pragma unroll
                for (int q = 0; q < 2; q++) {
                    mma16816(c2f[2 * nb2 + q], ah, bh[2 * q], bh[2 * q + 1]);
                    mma16816(c2f[2 * nb2 + q], ah, bl[2 * q], bl[2 * q + 1]);
                    mma16816(c2f[2 * nb2 + q], al, bh[2 * q], bh[2 * q + 1]);
                }
            }
        }

#pragma unroll
        for (int nb2 = 0; nb2 < 2; nb2++) {
#pragma unroll
            for (int q = 0; q < 2; q++) {
                int col = half * 128 + wn * 32 + nb2 * 16 + q * 8 + 2 * q4;
                float bj0 = b1[col], bj1 = b1[col + 1];
                int chunk = col >> 6, k2 = col & 63;
                const float* cf = c2f[2 * nb2 + q];
                __nv_bfloat162 hh0, ll0, hh1, ll1;
                split2(gelu_exact(cf[0] + bj0), gelu_exact(cf[1] + bj1), hh0, ll0);
                split2(gelu_exact(cf[2] + bj0), gelu_exact(cf[3] + bj1), hh1, ll1);
                uint32_t coff = (uint32_t)(FB_M + chunk * 8192);
                uint32_t sw0 = SW128((uint32_t)((wm * 16 + g) * 128 + k2 * 2));
                uint32_t sw1 = SW128((uint32_t)((wm * 16 + g + 8) * 128 + k2 * 2));
                *(__nv_bfloat162*)(smem + coff + sw0)        = hh0;
                *(__nv_bfloat162*)(smem + coff + 4096 + sw0) = ll0;
                *(__nv_bfloat162*)(smem + coff + sw1)        = hh1;
                *(__nv_bfloat162*)(smem + coff + 4096 + sw1) = ll1;
            }
        }
        __syncthreads();
    }

    float cC[2][4];
#pragma unroll
    for (int q = 0; q < 2; q++)
#pragma unroll
        for (int j = 0; j < 4; j++) cC[q][j] = 0.f;

    int b_n = wn * 16 + bn_sub;
    for (int pair = 0; pair < 2; pair++) {
        for (int i = tid; i < 2048; i += 256) {
            int cl = i >> 10;
            int rest = i & 1023;
            int hl = rest >> 9;
            int idx = rest & 511;
            int n = idx >> 3, c = idx & 7;
            uint32_t sw = SW128((uint32_t)(n * 128 + c * 16));
            const __nv_bfloat16* src = (hl ? g_w2Tl : g_w2Th)
                + (size_t)n * FM + (2 * pair + cl) * 64 + c * 8;
            *(uint4*)(smem + FB_W + cl * 16384 + hl * 8192 + sw) = *(const uint4*)src;
        }
        __syncthreads();

#pragma unroll
        for (int cl = 0; cl < 2; cl++) {
            int chunk = 2 * pair + cl;
            uint32_t Ah = sb + FB_M + chunk * 8192, Al = Ah + 4096;
            uint32_t Bh = sb + FB_W + cl * 16384,   Bl = Bh + 8192;
#pragma unroll
            for (int ks = 0; ks < 4; ks++) {
                uint32_t swa = SW128((uint32_t)(a_row * 128 + a_colb + ks * 32));
                uint32_t swb = SW128((uint32_t)(b_n * 128 + b_kb + ks * 32));
                uint32_t ah[4], al[4], bh[4], bl[4];
                ldm4(ah[0], ah[1], ah[2], ah[3], Ah + swa);
                ldm4(al[0], al[1], al[2], al[3], Al + swa);
                ldm4(bh[0], bh[1], bh[2], bh[3], Bh + swb);
                ldm4(bl[0], bl[1], bl[2], bl[3], Bl + swb);
#pragma unroll
                for (int q = 0; q < 2; q++) {
                    mma16816(cC[q], ah, bh[2 * q], bh[2 * q + 1]);
                    mma16816(cC[q], ah, bl[2 * q], bl[2 * q + 1]);
                    mma16816(cC[q], al, bh[2 * q], bh[2 * q + 1]);
                }
            }
        }
        __syncthreads();
    }

    // epilogue: +b2, fp16 split (lo scaled by 1024) -> g_yh / g_yl
#pragma unroll
    for (int q = 0; q < 2; q++) {
        int col = wn * 16 + q * 8 + 2 * q4;
        float b20 = b2[col], b21 = b2[col + 1];
        int r0 = rb + wm * 16 + g, r1 = r0 + 8;
        float y00 = cC[q][0] + b20, y01 = cC[q][1] + b21;
        float y10 = cC[q][2] + b20, y11 = cC[q][3] + b21;
        __half2 hh0, ll0, hh1, ll1;
        hh0.x = __float2half_rn(y00); hh0.y = __float2half_rn(y01);
        hh1.x = __float2half_rn(y10); hh1.y = __float2half_rn(y11);
        ll0.x = __float2half_rn((y00 - __half2float(hh0.x)) * 1024.0f);
        ll0.y = __float2half_rn((y01 - __half2float(hh0.y)) * 1024.0f);
        ll1.x = __float2half_rn((y10 - __half2float(hh1.x)) * 1024.0f);
        ll1.y = __float2half_rn((y11 - __half2float(hh1.y)) * 1024.0f);
        *(__half2*)(g_yh + r0 * 64 + col) = hh0;
        *(__half2*)(g_yl + r0 * 64 + col) = ll0;
        *(__half2*)(g_yh + r1 * 64 + col) = hh1;
        *(__half2*)(g_yl + r1 * 64 + col) = ll1;
    }
}

// ---------------------------------------------------------------------------
// 4) Logits GEMM, fp16 2-product: D = yh@Wh + (yl*1024)@Wh / 1024.
//    Persistent column-stripe, Wh resident (16KB), A dbuf (2x16KB). 48KB smem.
// ---------------------------------------------------------------------------
constexpr int S_BH = 0;
constexpr int S_A  = 16384;
constexpr int S_TOT = 49152;

__global__ void __launch_bounds__(256, 2)
k_logits_mma(const float* __restrict__ bf, float* __restrict__ out) {
    extern __shared__ char smem[];
    uint32_t sb = smem_u32(smem);
    int tid = threadIdx.x, wid = tid >> 5, lane = tid & 31;
    int nb = blockIdx.x * 128;
    int wm = wid & 1;
    int wn = wid >> 1;

    for (int idx = tid; idx < 1024; idx += 256) {
        int r = idx >> 3, c = idx & 7;
        uint32_t sw = SW128((uint32_t)(r * 128 + c * 16));
        *(uint4*)(smem + S_BH + sw) =
            *(const uint4*)(g_wh + (size_t)(nb + r) * 64 + c * 8);
    }

    int g = lane >> 2, q4 = lane & 3;
    float2 bias_r[4];
#pragma unroll
    for (int nbk = 0; nbk < 4; nbk++)
        bias_r[nbk] = *(const float2*)(bf + nb + wn * 32 + nbk * 8 + 2 * q4);

    {
        uint32_t ab = sb + S_A;
#pragma unroll
        for (int it2 = 0; it2 < 2; it2++) {
            int idx = tid + it2 * 256;
            int r = idx >> 3, c = idx & 7;
            uint32_t sw = SW128((uint32_t)(r * 128 + c * 16));
            size_t go = (size_t)r * 64 + c * 8;
            cpa16(ab + sw,        g_yh + go);
            cpa16(ab + 8192 + sw, g_yl + go);
        }
    }
    CPA_COMMIT();
    __syncthreads();

    int a_row  = wm * 32 + (lane & 15);
    int a_colb = (lane >> 4) * 16;
    int b_n    = wn * 32 + ((lane >> 3) >> 1) * 8 + (lane & 7);
    int b_kb   = ((lane >> 3) & 1) * 16;

    for (int it = 0; it < 50; it++) {
        int p = it & 1;
        if (it + 1 < 50) {
            uint32_t ab = sb + S_A + (1 - p) * 16384;
#pragma unroll
            for (int it2 = 0; it2 < 2; it2++) {
                int idx = tid + it2 * 256;
                int r = idx >> 3, c = idx & 7;
                uint32_t sw = SW128((uint32_t)(r * 128 + c * 16));
                size_t go = (size_t)((it + 1) * 64 + r) * 64 + c * 8;
                cpa16(ab + sw,        g_yh + go);
                cpa16(ab + 8192 + sw, g_yl + go);
            }
        }
        CPA_COMMIT();
        CPA_WAIT1();
        __syncthreads();

        float c[2][4][4], d[2][4][4];
#pragma unroll
        for (int mb = 0; mb < 2; mb++)
#pragma unroll
            for (int nbk = 0; nbk < 4; nbk++)
#pragma unroll
                for (int j = 0; j < 4; j++) { c[mb][nbk][j] = 0.f; d[mb][nbk][j] = 0.f; }

        uint32_t Ah = sb + S_A + p * 16384;
        uint32_t Al = Ah + 8192;
        uint32_t Bh = sb + S_BH;

#pragma unroll
        for (int ks = 0; ks < 4; ks++) {
            uint32_t swa0 = SW128((uint32_t)(a_row * 128 + a_colb + ks * 32));
            uint32_t swa1 = SW128((uint32_t)((a_row + 16) * 128 + a_colb + ks * 32));
            uint32_t swb0 = SW128((uint32_t)(b_n * 128 + b_kb + ks * 32));
            uint32_t swb1 = SW128((uint32_t)((b_n + 16) * 128 + b_kb + ks * 32));

            uint32_t ah0[4], ah1[4], al0[4], al1[4];
            uint32_t bh[8];
            ldm4(ah0[0], ah0[1], ah0[2], ah0[3], Ah + swa0);
            ldm4(ah1[0], ah1[1], ah1[2], ah1[3], Ah + swa1);
            ldm4(al0[0], al0[1], al0[2], al0[3], Al + swa0);
            ldm4(al1[0], al1[1], al1[2], al1[3], Al + swa1);
            ldm4(bh[0], bh[1], bh[2], bh[3], Bh + swb0);
            ldm4(bh[4], bh[5], bh[6], bh[7], Bh + swb1);

#pragma unroll
            for (int q = 0; q < 2; q++) {
                mma16816h(c[0][2 * q],     ah0, bh[4 * q],     bh[4 * q + 1]);
                mma16816h(c[0][2 * q + 1], ah0, bh[4 * q + 2], bh[4 * q + 3]);
                mma16816h(c[1][2 * q],     ah1, bh[4 * q],     bh[4 * q + 1]);
                mma16816h(c[1][2 * q + 1], ah1, bh[4 * q + 2], bh[4 * q + 3]);
                mma16816h(d[0][2 * q],     al0, bh[4 * q],     bh[4 * q + 1]);
                mma16816h(d[0][2 * q + 1], al0, bh[4 * q + 2], bh[4 * q + 3]);
                mma16816h(d[1][2 * q],     al1, bh[4 * q],     bh[4 * q + 1]);
                mma16816h(d[1][2 * q + 1], al1, bh[4 * q + 2], bh[4 * q + 3]);
            }
        }

        const float ds = 1.0f / 1024.0f;
#pragma unroll
        for (int mb = 0; mb < 2; mb++) {
            int row = it * 64 + wm * 32 + mb * 16 + g;
            float* orow = out + (size_t)row * NV;
#pragma unroll
            for (int nbk = 0; nbk < 4; nbk++) {
                int col = nb + wn * 32 + nbk * 8 + 2 * q4;
                float2 bv = bias_r[nbk];
                float2 v0 = make_float2(c[mb][nbk][0] + d[mb][nbk][0] * ds + bv.x,
                                        c[mb][nbk][1] + d[mb][nbk][1] * ds + bv.y);
                float2 v1 = make_float2(c[mb][nbk][2] + d[mb][nbk][2] * ds + bv.x,
                                        c[mb][nbk][3] + d[mb][nbk][3] * ds + bv.y);
                *(float2*)(orow + col)          = v0;
                *(float2*)(orow + 8 * NV + col) = v1;
            }
        }
        __syncthreads();
    }
}

// ---------------------------------------------------------------------------
extern "C" void kernel_launch(void* const* d_in, const int* in_sizes, int n_in,
                              void* d_out, int out_size) {
    (void)in_sizes; (void)n_in; (void)out_size;
    const int*   x  = (const int*)d_in[0];
    const float* te = (const float*)d_in[1];
    const float* pe = (const float*)d_in[2];
    const float* Wq = (const float*)d_in[3];  const float* bq = (const float*)d_in[4];
    const float* Wk = (const float*)d_in[5];  const float* bk = (const float*)d_in[6];
    const float* Wv = (const float*)d_in[7];  const float* bv = (const float*)d_in[8];
    const float* Wo = (const float*)d_in[9];  const float* bo = (const float*)d_in[10];
    const float* W1 = (const float*)d_in[11]; const float* b1 = (const float*)d_in[12];
    const float* W2 = (const float*)d_in[13]; const float* b2 = (const float*)d_in[14];
    const float* Wf = (const float*)d_in[15]; const float* bf = (const float*)d_in[16];
    float* out = (float*)d_out;

    k_cvt_all<<<524, 256>>>(Wf, Wo, W1, W2);
    k_qkv<<<dim3(B, H, 3), 128>>>(x, te, pe, Wq, bq, Wk, bk, Wv, bv);

    int attn_smem = A_TOTF * (int)sizeof(float);
    cudaFuncSetAttribute(k_attn, cudaFuncAttributeMaxDynamicSharedMemorySize, attn_smem);
    k_attn<<<dim3(B, H), 256, attn_smem>>>();

    k_ffn_a<<<BT / 32, 256>>>(bo);

    cudaFuncSetAttribute(k_ffn_b, cudaFuncAttributeMaxDynamicSharedMemorySize, FB_TOT);
    k_ffn_b<<<BT / 32, 256, FB_TOT>>>(b1, b2);

    cudaFuncSetAttribute(k_logits_mma, cudaFuncAttributeMaxDynamicSharedMemorySize, S_TOT);
    k_logits_mma<<<NV / 128, 256, S_TOT>>>(bf, out);
}

// round 17
// speedup vs baseline: 1.5578x; 1.1121x over previous
#include <cuda_runtime.h>
#include <cuda_bf16.h>
#include <cuda_fp16.h>
#include <math.h>
#include <cstdint>

// ---------------------------------------------------------------------------
// SimpleGPT forward. R17: k_ffn_a rebuilt — grid 200 (16 rows/block),
// cp.async double-buffered k-chunks, 8 n8-warps. Rest = R16 (264.7us).
// B=64 T=50 V=32000 E=64 DH=128 H=8 M=256
// ---------------------------------------------------------------------------
constexpr int B   = 64;
constexpr int T   = 50;
constexpr int NV  = 32000;
constexpr int E   = 64;
constexpr int DH  = 128;
constexpr int H   = 8;
constexpr int FM  = 256;
constexpr int BT  = B * T;
constexpr int OD  = H * DH;

typedef unsigned long long u64;

__device__ __forceinline__ u64 ffma2(u64 a, u64 b, u64 c) {
    u64 d;
    asm("fma.rn.f32x2 %0, %1, %2, %3;" : "=l"(d) : "l"(a), "l"(b), "l"(c));
    return d;
}
__device__ __forceinline__ u64 bcast2(float x) {
    u64 d;
    unsigned xi = __float_as_uint(x);
    asm("mov.b64 %0, {%1, %1};" : "=l"(d) : "r"(xi));
    return d;
}
__device__ __forceinline__ u64 pack2f(float x, float y) {
    u64 d;
    unsigned xi = __float_as_uint(x), yi = __float_as_uint(y);
    asm("mov.b64 %0, {%1, %2};" : "=l"(d) : "r"(xi), "r"(yi));
    return d;
}
__device__ __forceinline__ u64 pk(uint32_t lo, uint32_t hi) {
    u64 d;
    asm("mov.b64 %0, {%1, %2};" : "=l"(d) : "r"(lo), "r"(hi));
    return d;
}
__device__ __forceinline__ float2 unpack2(u64 v) {
    unsigned lo, hi;
    asm("mov.b64 {%0, %1}, %2;" : "=r"(lo), "=r"(hi) : "l"(v));
    return make_float2(__uint_as_float(lo), __uint_as_float(hi));
}
__device__ __forceinline__ uint32_t smem_u32(const void* p) {
    uint32_t a;
    asm("{ .reg .u64 t; cvta.to.shared.u64 t, %1; cvt.u32.u64 %0, t; }" : "=r"(a) : "l"(p));
    return a;
}
__device__ __forceinline__ void cpa16(uint32_t saddr, const void* gptr) {
    asm volatile("cp.async.cg.shared.global [%0], [%1], 16;"
                 :: "r"(saddr), "l"(__cvta_generic_to_global(gptr)) : "memory");
}
#define CPA_COMMIT() asm volatile("cp.async.commit_group;" ::: "memory")
#define CPA_WAIT1()  asm volatile("cp.async.wait_group 1;" ::: "memory")
#define SW128(x) ((x) ^ (((x) >> 3) & 0x70))

__device__ __forceinline__ float gelu_exact(float x) {
    return 0.5f * x * (1.0f + erff(x * 0.70710678118654752f));
}
__device__ __forceinline__ void split2(float v0, float v1,
                                       __nv_bfloat162& hh, __nv_bfloat162& ll) {
    __nv_bfloat16 h0 = __float2bfloat16_rn(v0);
    __nv_bfloat16 h1 = __float2bfloat16_rn(v1);
    hh.x = h0; hh.y = h1;
    ll.x = __float2bfloat16_rn(v0 - __bfloat162float(h0));
    ll.y = __float2bfloat16_rn(v1 - __bfloat162float(h1));
}

// Scratch (device globals — referenced ONLY from device code)
__device__ __align__(16) float g_q[B * H * T * DH];
__device__ __align__(16) float g_k[B * H * T * DH];
__device__ __align__(16) float g_v[B * H * T * DH];
__device__ __align__(16) __nv_bfloat16 g_oh[BT * OD];
__device__ __align__(16) __nv_bfloat16 g_ol[BT * OD];
__device__ __align__(16) __nv_bfloat16 g_ah[BT * E];
__device__ __align__(16) __nv_bfloat16 g_al[BT * E];
__device__ __align__(16) __half g_yh[BT * E];
__device__ __align__(16) __half g_yl[BT * E];
__device__ __align__(16) __half g_wh[(size_t)NV * E];
__device__ __align__(16) __nv_bfloat16 g_woTh[OD * E];
__device__ __align__(16) __nv_bfloat16 g_woTl[OD * E];
__device__ __align__(16) __nv_bfloat16 g_w1Th[FM * E];
__device__ __align__(16) __nv_bfloat16 g_w1Tl[FM * E];
__device__ __align__(16) __nv_bfloat16 g_w2Th[E * FM];
__device__ __align__(16) __nv_bfloat16 g_w2Tl[E * FM];

// ---------------------------------------------------------------------------
// 0) ALL weight conversions in one launch (R16, validated)
// ---------------------------------------------------------------------------
__global__ void k_cvt_all(const float* __restrict__ Wf,
                          const float* __restrict__ Wo,
                          const float* __restrict__ W1,
                          const float* __restrict__ W2) {
    __shared__ float s[64 * 65];
    int tid = threadIdx.x;
    int bid = blockIdx.x;

    if (bid < 500) {
        int nb = bid * 64;
#pragma unroll
        for (int it = 0; it < 16; it++) {
            int i = tid + it * 256;
            int k = i >> 6, j = i & 63;
            s[k * 65 + j] = Wf[(size_t)k * NV + nb + j];
        }
        __syncthreads();
#pragma unroll
        for (int it = 0; it < 8; it++) {
            int i = tid + it * 256;
            int n = i >> 5, k2 = (i & 31) * 2;
            __half2 hh;
            hh.x = __float2half_rn(s[k2 * 65 + n]);
            hh.y = __float2half_rn(s[(k2 + 1) * 65 + n]);
            *(__half2*)(g_wh + (size_t)(nb + n) * 64 + k2) = hh;
        }
        return;
    }

    int r = bid - 500;
    const float* in;
    __nv_bfloat16 *oh, *ol;
    int R, C, cb, rb;
    if (r < 16)      { in = Wo; oh = g_woTh; ol = g_woTl; R = OD; C = E;  cb = 0;      rb = r * 64; }
    else if (r < 20) { in = W1; oh = g_w1Th; ol = g_w1Tl; R = E;  C = FM; cb = (r - 16) * 64; rb = 0; }
    else             { in = W2; oh = g_w2Th; ol = g_w2Tl; R = FM; C = E;  cb = 0;      rb = (r - 20) * 64; }

#pragma unroll
    for (int it = 0; it < 16; it++) {
        int i = tid + it * 256;
        int rr = i >> 6, c = i & 63;
        s[rr * 65 + c] = in[(size_t)(rb + rr) * C + cb + c];
    }
    __syncthreads();
#pragma unroll
    for (int it = 0; it < 8; it++) {
        int i = tid + it * 256;
        int n = i >> 5, k2 = (i & 31) * 2;
        __nv_bfloat162 hh, ll;
        split2(s[k2 * 65 + n], s[(k2 + 1) * 65 + n], hh, ll);
        size_t o = (size_t)(cb + n) * R + rb + k2;
        *(__nv_bfloat162*)(oh + o) = hh;
        *(__nv_bfloat162*)(ol + o) = ll;
    }
}

// ---------------------------------------------------------------------------
// 1) QKV (+ fused embedding)
// ---------------------------------------------------------------------------
__global__ void k_qkv(const int* __restrict__ x,
                      const float* __restrict__ te, const float* __restrict__ pe,
                      const float* __restrict__ Wq, const float* __restrict__ bq,
                      const float* __restrict__ Wk, const float* __restrict__ bk,
                      const float* __restrict__ Wv, const float* __restrict__ bv) {
    __shared__ __align__(16) float h_s[T * E];
    int b = blockIdx.x, h = blockIdx.y, m = blockIdx.z;
    int d = threadIdx.x;

    for (int i = d; i < T * E; i += 128) {
        int t = i >> 6;
        h_s[i] = te[x[b * T + t] * E + (i & 63)] + pe[i];
    }

    const float* W    = (m == 0) ? Wq : ((m == 1) ? Wk : Wv);
    const float* bias = (m == 0) ? bq : ((m == 1) ? bk : bv);
    float* out = ((m == 0) ? g_q : ((m == 1) ? g_k : g_v)) + ((size_t)(b * H + h) * T) * DH;

    u64 wp[32];
#pragma unroll
    for (int e2 = 0; e2 < 32; e2++)
        wp[e2] = pack2f(W[(h * E + 2 * e2) * DH + d], W[(h * E + 2 * e2 + 1) * DH + d]);
    float bb = bias[h * DH + d];
    __syncthreads();

    for (int t = 0; t < T; t++) {
        u64 a0 = 0ull, a1 = 0ull;
        const u64* hp = (const u64*)(h_s + t * E);
#pragma unroll
        for (int e2 = 0; e2 < 32; e2 += 2) {
            a0 = ffma2(wp[e2],     hp[e2],     a0);
            a1 = ffma2(wp[e2 + 1], hp[e2 + 1], a1);
        }
        float2 s0 = unpack2(a0), s1 = unpack2(a1);
        out[t * DH + d] = s0.x + s0.y + s1.x + s1.y + bb;
    }
}

// ---------------------------------------------------------------------------
// 2) Attention (R6 core; epilogue emits bf16 hi/lo o)
// ---------------------------------------------------------------------------
constexpr int KP132 = 132;
constexpr int A_KOFF = T * KP132;
constexpr int A_VOFF = A_KOFF + T * DH;
constexpr int A_QOFF = A_VOFF;
constexpr int A_POFF = A_QOFF + 8 * 8 * DH;
constexpr int A_TOTF = A_POFF + 8 * 8 * 64;

__global__ void __launch_bounds__(256)
k_attn() {
    extern __shared__ float sm[];
    float* K_s = sm;
    float* V_s = sm + A_KOFF;
    float* q_s = sm + A_QOFF;
    float* p_s = sm + A_POFF;

    int b = blockIdx.x, h = blockIdx.y;
    int tid = threadIdx.x, w = tid >> 5, lane = tid & 31;
    size_t base = ((size_t)(b * H + h) * T) * DH;

    for (int i = tid; i < T * 32; i += 256) {
        int s = i >> 5, c4 = (i & 31) * 4;
        *(float4*)(K_s + s * KP132 + c4) = *(const float4*)(g_k + base + s * DH + c4);
        *(float4*)(V_s + s * DH + c4)    = *(const float4*)(g_v + base + s * DH + c4);
    }
    __syncthreads();

#pragma unroll
    for (int j = 0; j < 7; j++) {
        int t = w + 8 * j;
        if (t < T)
            *(float4*)(q_s + (w * 8 + j) * DH + lane * 4) =
                *(const float4*)(g_q + base + (size_t)t * DH + lane * 4);
    }
    __syncwarp();

    int s0 = lane, s1 = lane + 32;
    const float* k0p = K_s + s0 * KP132;
    const float* k1p = K_s + s1 * KP132;

    u64 acc[7][2];
#pragma unroll
    for (int j = 0; j < 7; j++) { acc[j][0] = 0ull; acc[j][1] = 0ull; }

#pragma unroll 8
    for (int c = 0; c < DH; c += 4) {
        uint4 k0 = *(const uint4*)(k0p + c);
        uint4 k1 = *(const uint4*)(k1p + c);
        u64 k0a = pk(k0.x, k0.y), k0b = pk(k0.z, k0.w);
        u64 k1a = pk(k1.x, k1.y), k1b = pk(k1.z, k1.w);
#pragma unroll
        for (int j = 0; j < 7; j++) {
            uint4 qv = *(const uint4*)(q_s + (w * 8 + j) * DH + c);
            u64 qa = pk(qv.x, qv.y), qb = pk(qv.z, qv.w);
            acc[j][0] = ffma2(qb, k0b, ffma2(qa, k0a, acc[j][0]));
            acc[j][1] = ffma2(qb, k1b, ffma2(qa, k1a, acc[j][1]));
        }
    }

    const float scale = 0.0883883476483184f;
    float sum[7], inv[7];
#pragma unroll
    for (int j = 0; j < 7; j++) {
        int t = w + 8 * j;
        bool valid = t < T;
        float2 f0 = unpack2(acc[j][0]);
        float2 f1 = unpack2(acc[j][1]);
        float sc0 = (f0.x + f0.y) * scale;
        float sc1 = (f1.x + f1.y) * scale;
        float e0 = (valid && s0 <= t) ? __expf(sc0) : 0.f;
        float e1 = (valid && s1 <= t) ? __expf(sc1) : 0.f;
        p_s[(w * 8 + j) * 64 + s0] = e0;
        p_s[(w * 8 + j) * 64 + s1] = e1;
        sum[j] = e0 + e1;
    }
#pragma unroll
    for (int off = 16; off; off >>= 1) {
#pragma unroll
        for (int j = 0; j < 7; j++)
            sum[j] += __shfl_xor_sync(0xffffffffu, sum[j], off);
    }
#pragma unroll
    for (int j = 0; j < 7; j++) inv[j] = 1.0f / sum[j];
    __syncwarp();

    u64 av[7][2];
#pragma unroll
    for (int j = 0; j < 7; j++) { av[j][0] = 0ull; av[j][1] = 0ull; }

    const float* vb = V_s + lane * 4;
    const float* pb = p_s + w * 8 * 64;
#pragma unroll 2
    for (int s = 0; s < T; s++) {
        uint4 vv = *(const uint4*)(vb + s * DH);
        u64 v01 = pk(vv.x, vv.y), v23 = pk(vv.z, vv.w);
#pragma unroll
        for (int j = 0; j < 7; j++) {
            u64 pj = bcast2(pb[j * 64 + s]);
            av[j][0] = ffma2(pj, v01, av[j][0]);
            av[j][1] = ffma2(pj, v23, av[j][1]);
        }
    }

#pragma unroll
    for (int j = 0; j < 7; j++) {
        int t = w + 8 * j;
        if (t < T) {
            float2 o01 = unpack2(av[j][0]), o23 = unpack2(av[j][1]);
            __nv_bfloat162 hA, lA, hB, lB;
            split2(o01.x * inv[j], o01.y * inv[j], hA, lA);
            split2(o23.x * inv[j], o23.y * inv[j], hB, lB);
            size_t o = (size_t)(b * T + t) * OD + h * DH + lane * 4;
            *(__nv_bfloat162*)(g_oh + o)     = hA;
            *(__nv_bfloat162*)(g_oh + o + 2) = hB;
            *(__nv_bfloat162*)(g_ol + o)     = lA;
            *(__nv_bfloat162*)(g_ol + o + 2) = lB;
        }
    }
}

// ---------------------------------------------------------------------------
// mma.sync helpers
// ---------------------------------------------------------------------------
__device__ __forceinline__ void ldm4(uint32_t& r0, uint32_t& r1,
                                     uint32_t& r2, uint32_t& r3, uint32_t addr) {
    asm volatile("ldmatrix.sync.aligned.m8n8.x4.shared.b16 {%0,%1,%2,%3}, [%4];"
                 : "=r"(r0), "=r"(r1), "=r"(r2), "=r"(r3) : "r"(addr));
}
__device__ __forceinline__ void ldm2(uint32_t& r0, uint32_t& r1, uint32_t addr) {
    asm volatile("ldmatrix.sync.aligned.m8n8.x2.shared.b16 {%0,%1}, [%2];"
                 : "=r"(r0), "=r"(r1) : "r"(addr));
}
__device__ __forceinline__ void mma16816(float* c, const uint32_t* a,
                                         uint32_t b0, uint32_t b1) {
    asm volatile(
        "mma.sync.aligned.m16n8k16.row.col.f32.bf16.bf16.f32 "
        "{%0,%1,%2,%3}, {%4,%5,%6,%7}, {%8,%9}, {%0,%1,%2,%3};"
        : "+f"(c[0]), "+f"(c[1]), "+f"(c[2]), "+f"(c[3])
        : "r"(a[0]), "r"(a[1]), "r"(a[2]), "r"(a[3]), "r"(b0), "r"(b1));
}
__device__ __forceinline__ void mma16816h(float* c, const uint32_t* a,
                                          uint32_t b0, uint32_t b1) {
    asm volatile(
        "mma.sync.aligned.m16n8k16.row.col.f32.f16.f16.f32 "
        "{%0,%1,%2,%3}, {%4,%5,%6,%7}, {%8,%9}, {%0,%1,%2,%3};"
        : "+f"(c[0]), "+f"(c[1]), "+f"(c[2]), "+f"(c[3])
        : "r"(a[0]), "r"(a[1]), "r"(a[2]), "r"(a[3]), "r"(b0), "r"(b1));
}

// ---------------------------------------------------------------------------
// 3a) FFN stage A v2: a = o @ Wo + bo. 16 rows/block (grid 200), 8 n8-warps,
//     cp.async double-buffered k-chunks (A 4KB + B 16KB per chunk, 40KB smem).
// ---------------------------------------------------------------------------
constexpr int FA_CH = 20480;     // bytes per chunk buffer

__global__ void __launch_bounds__(256)
k_ffn_a(const float* __restrict__ bo) {
    __shared__ __align__(16) char smem[2 * FA_CH];  // 40KB static
    uint32_t sb = smem_u32(smem);
    int tid = threadIdx.x, wid = tid >> 5, lane = tid & 31;
    int rb = blockIdx.x * 16;
    int wn = wid;                 // n stripe: cols wn*8..+7

    int g = lane >> 2, q4 = lane & 3;
    int a_row  = lane & 15;
    int a_colb = (lane >> 4) * 16;
    int b_n8   = wn * 8 + (lane & 7);
    int b_kb2  = ((lane >> 3) & 1) * 16;

    auto stage = [&](int kc, int buf) {
        uint32_t base = sb + buf * FA_CH;
        // A: 16 rows x 64k x 2B x 2 halves = 4KB (256 x 16B)
        {
            int i = tid;
            int half = i >> 7, r = (i >> 3) & 15, c = i & 7;
            uint32_t sw = SW128((uint32_t)(r * 128 + c * 16));
            const __nv_bfloat16* src =
                (half ? g_ol : g_oh) + (size_t)(rb + r) * OD + kc * 64 + c * 8;
            cpa16(base + half * 2048 + sw, src);
        }
        // B: 64 n x 64k x 2B x 2 halves = 16KB (1024 x 16B)
        for (int i = tid; i < 1024; i += 256) {
            int half = i >> 9, n = (i >> 3) & 63, c = i & 7;
            uint32_t sw = SW128((uint32_t)(n * 128 + c * 16));
            const __nv_bfloat16* src =
                (half ? g_woTl : g_woTh) + (size_t)n * OD + kc * 64 + c * 8;
            cpa16(base + 4096 + half * 8192 + sw, src);
        }
    };

    float cA[4] = {0.f, 0.f, 0.f, 0.f};

    stage(0, 0);
    CPA_COMMIT();
    for (int kc = 0; kc < 16; kc++) {
        int p = kc & 1;
        if (kc + 1 < 16) stage(kc + 1, 1 - p);
        CPA_COMMIT();
        CPA_WAIT1();
        __syncthreads();

        uint32_t Ah = sb + p * FA_CH;
        uint32_t Al = Ah + 2048;
        uint32_t Bh = Ah + 4096;
        uint32_t Bl = Ah + 12288;
#pragma unroll
        for (int ks = 0; ks < 4; ks++) {
            uint32_t swa = SW128((uint32_t)(a_row * 128 + a_colb + ks * 32));
            uint32_t swb = SW128((uint32_t)(b_n8 * 128 + b_kb2 + ks * 32));
            uint32_t ah[4], al[4], bh0, bh1, bl0, bl1;
            ldm4(ah[0], ah[1], ah[2], ah[3], Ah + swa);
            ldm4(al[0], al[1], al[2], al[3], Al + swa);
            ldm2(bh0, bh1, Bh + swb);
            ldm2(bl0, bl1, Bl + swb);
            mma16816(cA, ah, bh0, bh1);
            mma16816(cA, ah, bl0, bl1);
            mma16816(cA, al, bh0, bh1);
        }
        __syncthreads();   // buffer p reused for staging kc+2 next iteration
    }

    // epilogue: warp wn covers cols wn*8 + 2*q4 (+1); rows rb+g, rb+g+8
    {
        int col = wn * 8 + 2 * q4;
        float b0 = bo[col], b1v = bo[col + 1];
        int r0 = rb + g, r1 = r0 + 8;
        __nv_bfloat162 hh0, ll0, hh1, ll1;
        split2(cA[0] + b0, cA[1] + b1v, hh0, ll0);
        split2(cA[2] + b0, cA[3] + b1v, hh1, ll1);
        *(__nv_bfloat162*)(g_ah + r0 * 64 + col) = hh0;
        *(__nv_bfloat162*)(g_al + r0 * 64 + col) = ll0;
        *(__nv_bfloat162*)(g_ah + r1 * 64 + col) = hh1;
        *(__nv_bfloat162*)(g_al + r1 * 64 + col) = ll1;
    }
}

// ---------------------------------------------------------------------------
// 3b) FFN stage B+C (R16, validated)
// ---------------------------------------------------------------------------
constexpr int FB_W = 0;
constexpr int FB_A = 32768;
constexpr int FB_M = 40960;
constexpr int FB_TOT = 73728;

__global__ void __launch_bounds__(256)
k_ffn_b(const float* __restrict__ b1, const float* __restrict__ b2) {
    extern __shared__ char smem[];
    uint32_t sb = smem_u32(smem);
    int tid = threadIdx.x, wid = tid >> 5, lane = tid & 31;
    int rb = blockIdx.x * 32;
    int wm = wid & 1;
    int wn = wid >> 1;

    int g = lane >> 2, q4 = lane & 3;
    int a_row  = wm * 16 + (lane & 15);
    int a_colb = (lane >> 4) * 16;
    int bn_sub = ((lane >> 3) >> 1) * 8 + (lane & 7);
    int b_kb   = ((lane >> 3) & 1) * 16;

    for (int i = tid; i < 512; i += 256) {
        int half = i >> 8, r = (i >> 3) & 31, c = i & 7;
        uint32_t sw = SW128((uint32_t)(r * 128 + c * 16));
        const __nv_bfloat16* src =
            (half ? g_al : g_ah) + (size_t)(rb + r) * 64 + c * 8;
        *(uint4*)(smem + FB_A + half * 4096 + sw) = *(const uint4*)src;
    }

    for (int half = 0; half < 2; half++) {
        for (int i = tid; i < 2048; i += 256) {
            int hl = i >> 10;
            int idx = i & 1023;
            int nl = idx >> 3, c = idx & 7;
            uint32_t sw = SW128((uint32_t)(nl * 128 + c * 16));
            const __nv_bfloat16* src = (hl ? g_w1Tl : g_w1Th)
                + (size_t)(half * 128 + nl) * 64 + c * 8;
            *(uint4*)(smem + FB_W + hl * 16384 + sw) = *(const uint4*)src;
        }
        __syncthreads();

        float c2f[4][4];
#pragma unroll
        for (int i = 0; i < 4; i++)
#pragma unroll
            for (int j = 0; j < 4; j++) c2f[i][j] = 0.f;

        uint32_t Ah = sb + FB_A, Al = Ah + 4096;
        uint32_t Bh = sb + FB_W, Bl = Bh + 16384;
#pragma unroll
        for (int ks = 0; ks < 4; ks++) {
            uint32_t swa = SW128((uint32_t)(a_row * 128 + a_colb + ks * 32));
            uint32_t ah[4], al[4];
            ldm4(ah[0], ah[1], ah[2], ah[3], Ah + swa);
            ldm4(al[0], al[1], al[2], al[3], Al + swa);
#pragma unroll
            for (int nb2 = 0; nb2 < 2; nb2++) {
                int rowl = wn * 32 + nb2 * 16 + bn_sub;
                uint32_t swb = SW128((uint32_t)(rowl * 128 + b_kb + ks * 32));
                uint32_t bh[4], bl[4];
                ldm4(bh[0], bh[1], bh[2], bh[3], Bh + swb);
                ldm4(bl[0], bl[1], bl[2], bl[3], Bl + swb);
#pragma unroll
                for (int q = 0; q < 2; q++) {
                    mma16816(c2f[2 * nb2 + q], ah, bh[2 * q], bh[2 * q + 1]);
                    mma16816(c2f[2 * nb2 + q], ah, bl[2 * q], bl[2 * q + 1]);
                    mma16816(c2f[2 * nb2 + q], al, bh[2 * q], bh[2 * q + 1]);
                }
            }
        }

#pragma unroll
        for (int nb2 = 0; nb2 < 2; nb2++) {
#pragma unroll
            for (int q = 0; q < 2; q++) {
                int col = half * 128 + wn * 32 + nb2 * 16 + q * 8 + 2 * q4;
                float bj0 = b1[col], bj1 = b1[col + 1];
                int chunk = col >> 6, k2 = col & 63;
                const float* cf = c2f[2 * nb2 + q];
                __nv_bfloat162 hh0, ll0, hh1, ll1;
                split2(gelu_exact(cf[0] + bj0), gelu_exact(cf[1] + bj1), hh0, ll0);
                split2(gelu_exact(cf[2] + bj0), gelu_exact(cf[3] + bj1), hh1, ll1);
                uint32_t coff = (uint32_t)(FB_M + chunk * 8192);
                uint32_t sw0 = SW128((uint32_t)((wm * 16 + g) * 128 + k2 * 2));
                uint32_t sw1 = SW128((uint32_t)((wm * 16 + g + 8) * 128 + k2 * 2));
                *(__nv_bfloat162*)(smem + coff + sw0)        = hh0;
                *(__nv_bfloat162*)(smem + coff + 4096 + sw0) = ll0;
                *(__nv_bfloat162*)(smem + coff + sw1)        = hh1;
                *(__nv_bfloat162*)(smem + coff + 4096 + sw1) = ll1;
            }
        }
        __syncthreads();
    }

    float cC[2][4];
#pragma unroll
    for (int q = 0; q < 2; q++)
#pragma unroll
        for (int j = 0; j < 4; j++) cC[q][j] = 0.f;

    int b_n = wn * 16 + bn_sub;
    for (int pair = 0; pair < 2; pair++) {
        for (int i = tid; i < 2048; i += 256) {
            int cl = i >> 10;
            int rest = i & 1023;
            int hl = rest >> 9;
            int idx = rest & 511;
            int n = idx >> 3, c = idx & 7;
            uint32_t sw = SW128((uint32_t)(n * 128 + c * 16));
            const __nv_bfloat16* src = (hl ? g_w2Tl : g_w2Th)
                + (size_t)n * FM + (2 * pair + cl) * 64 + c * 8;
            *(uint4*)(smem + FB_W + cl * 16384 + hl * 8192 + sw) = *(const uint4*)src;
        }
        __syncthreads();

#pragma unroll
        for (int cl = 0; cl < 2; cl++) {
            int chunk = 2 * pair + cl;
            uint32_t Ah = sb + FB_M + chunk * 8192, Al = Ah + 4096;
            uint32_t Bh = sb + FB_W + cl * 16384,   Bl = Bh + 8192;
#pragma unroll
            for (int ks = 0; ks < 4; ks++) {
                uint32_t swa = SW128((uint32_t)(a_row * 128 + a_colb + ks * 32));
                uint32_t swb = SW128((uint32_t)(b_n * 128 + b_kb + ks * 32));
                uint32_t ah[4], al[4], bh[4], bl[4];
                ldm4(ah[0], ah[1], ah[2], ah[3], Ah + swa);
                ldm4(al[0], al[1], al[2], al[3], Al + swa);
                ldm4(bh[0], bh[1], bh[2], bh[3], Bh + swb);
                ldm4(bl[0], bl[1], bl[2], bl[3], Bl + swb);
#pragma unroll
                for (int q = 0; q < 2; q++) {
                    mma16816(cC[q], ah, bh[2 * q], bh[2 * q + 1]);
                    mma16816(cC[q], ah, bl[2 * q], bl[2 * q + 1]);
                    mma16816(cC[q], al, bh[2 * q], bh[2 * q + 1]);
                }
            }
        }
        __syncthreads();
    }

#pragma unroll
    for (int q = 0; q < 2; q++) {
        int col = wn * 16 + q * 8 + 2 * q4;
        float b20 = b2[col], b21 = b2[col + 1];
        int r0 = rb + wm * 16 + g, r1 = r0 + 8;
        float y00 = cC[q][0] + b20, y01 = cC[q][1] + b21;
        float y10 = cC[q][2] + b20, y11 = cC[q][3] + b21;
        __half2 hh0, ll0, hh1, ll1;
        hh0.x = __float2half_rn(y00); hh0.y = __float2half_rn(y01);
        hh1.x = __float2half_rn(y10); hh1.y = __float2half_rn(y11);
        ll0.x = __float2half_rn((y00 - __half2float(hh0.x)) * 1024.0f);
        ll0.y = __float2half_rn((y01 - __half2float(hh0.y)) * 1024.0f);
        ll1.x = __float2half_rn((y10 - __half2float(hh1.x)) * 1024.0f);
        ll1.y = __float2half_rn((y11 - __half2float(hh1.y)) * 1024.0f);
        *(__half2*)(g_yh + r0 * 64 + col) = hh0;
        *(__half2*)(g_yl + r0 * 64 + col) = ll0;
        *(__half2*)(g_yh + r1 * 64 + col) = hh1;
        *(__half2*)(g_yl + r1 * 64 + col) = ll1;
    }
}

// ---------------------------------------------------------------------------
// 4) Logits GEMM, fp16 2-product (R14/R16, validated 2.085e-4)
// ---------------------------------------------------------------------------
constexpr int S_BH = 0;
constexpr int S_A  = 16384;
constexpr int S_TOT = 49152;

__global__ void __launch_bounds__(256, 2)
k_logits_mma(const float* __restrict__ bf, float* __restrict__ out) {
    extern __shared__ char smem[];
    uint32_t sb = smem_u32(smem);
    int tid = threadIdx.x, wid = tid >> 5, lane = tid & 31;
    int nb = blockIdx.x * 128;
    int wm = wid & 1;
    int wn = wid >> 1;

    for (int idx = tid; idx < 1024; idx += 256) {
        int r = idx >> 3, c = idx & 7;
        uint32_t sw = SW128((uint32_t)(r * 128 + c * 16));
        *(uint4*)(smem + S_BH + sw) =
            *(const uint4*)(g_wh + (size_t)(nb + r) * 64 + c * 8);
    }

    int g = lane >> 2, q4 = lane & 3;
    float2 bias_r[4];
#pragma unroll
    for (int nbk = 0; nbk < 4; nbk++)
        bias_r[nbk] = *(const float2*)(bf + nb + wn * 32 + nbk * 8 + 2 * q4);

    {
        uint32_t ab = sb + S_A;
#pragma unroll
        for (int it2 = 0; it2 < 2; it2++) {
            int idx = tid + it2 * 256;
            int r = idx >> 3, c = idx & 7;
            uint32_t sw = SW128((uint32_t)(r * 128 + c * 16));
            size_t go = (size_t)r * 64 + c * 8;
            cpa16(ab + sw,        g_yh + go);
            cpa16(ab + 8192 + sw, g_yl + go);
        }
    }
    CPA_COMMIT();
    __syncthreads();

    int a_row  = wm * 32 + (lane & 15);
    int a_colb = (lane >> 4) * 16;
    int b_n    = wn * 32 + ((lane >> 3) >> 1) * 8 + (lane & 7);
    int b_kb   = ((lane >> 3) & 1) * 16;

    for (int it = 0; it < 50; it++) {
        int p = it & 1;
        if (it + 1 < 50) {
            uint32_t ab = sb + S_A + (1 - p) * 16384;
#pragma unroll
            for (int it2 = 0; it2 < 2; it2++) {
                int idx = tid + it2 * 256;
                int r = idx >> 3, c = idx & 7;
                uint32_t sw = SW128((uint32_t)(r * 128 + c * 16));
                size_t go = (size_t)((it + 1) * 64 + r) * 64 + c * 8;
                cpa16(ab + sw,        g_yh + go);
                cpa16(ab + 8192 + sw, g_yl + go);
            }
        }
        CPA_COMMIT();
        CPA_WAIT1();
        __syncthreads();

        float c[2][4][4], d[2][4][4];
#pragma unroll
        for (int mb = 0; mb < 2; mb++)
#pragma unroll
            for (int nbk = 0; nbk < 4; nbk++)
#pragma unroll
                for (int j = 0; j < 4; j++) { c[mb][nbk][j] = 0.f; d[mb][nbk][j] = 0.f; }

        uint32_t Ah = sb + S_A + p * 16384;
        uint32_t Al = Ah + 8192;
        uint32_t Bh = sb + S_BH;

#pragma unroll
        for (int ks = 0; ks < 4; ks++) {
            uint32_t swa0 = SW128((uint32_t)(a_row * 128 + a_colb + ks * 32));
            uint32_t swa1 = SW128((uint32_t)((a_row + 16) * 128 + a_colb + ks * 32));
            uint32_t swb0 = SW128((uint32_t)(b_n * 128 + b_kb + ks * 32));
            uint32_t swb1 = SW128((uint32_t)((b_n + 16) * 128 + b_kb + ks * 32));

            uint32_t ah0[4], ah1[4], al0[4], al1[4];
            uint32_t bh[8];
            ldm4(ah0[0], ah0[1], ah0[2], ah0[3], Ah + swa0);
            ldm4(ah1[0], ah1[1], ah1[2], ah1[3], Ah + swa1);
            ldm4(al0[0], al0[1], al0[2], al0[3], Al + swa0);
            ldm4(al1[0], al1[1], al1[2], al1[3], Al + swa1);
            ldm4(bh[0], bh[1], bh[2], bh[3], Bh + swb0);
            ldm4(bh[4], bh[5], bh[6], bh[7], Bh + swb1);

#pragma unroll
            for (int q = 0; q < 2; q++) {
                mma16816h(c[0][2 * q],     ah0, bh[4 * q],     bh[4 * q + 1]);
                mma16816h(c[0][2 * q + 1], ah0, bh[4 * q + 2], bh[4 * q + 3]);
                mma16816h(c[1][2 * q],     ah1, bh[4 * q],     bh[4 * q + 1]);
                mma16816h(c[1][2 * q + 1], ah1, bh[4 * q + 2], bh[4 * q + 3]);
                mma16816h(d[0][2 * q],     al0, bh[4 * q],     bh[4 * q + 1]);
                mma16816h(d[0][2 * q + 1], al0, bh[4 * q + 2], bh[4 * q + 3]);
                mma16816h(d[1][2 * q],     al1, bh[4 * q],     bh[4 * q + 1]);
                mma16816h(d[1][2 * q + 1], al1, bh[4 * q + 2], bh[4 * q + 3]);
            }
        }

        const float ds = 1.0f / 1024.0f;
#pragma unroll
        for (int mb = 0; mb < 2; mb++) {
            int row = it * 64 + wm * 32 + mb * 16 + g;
            float* orow = out + (size_t)row * NV;
#pragma unroll
            for (int nbk = 0; nbk < 4; nbk++) {
                int col = nb + wn * 32 + nbk * 8 + 2 * q4;
                float2 bv = bias_r[nbk];
                float2 v0 = make_float2(c[mb][nbk][0] + d[mb][nbk][0] * ds + bv.x,
                                        c[mb][nbk][1] + d[mb][nbk][1] * ds + bv.y);
                float2 v1 = make_float2(c[mb][nbk][2] + d[mb][nbk][2] * ds + bv.x,
                                        c[mb][nbk][3] + d[mb][nbk][3] * ds + bv.y);
                *(float2*)(orow + col)          = v0;
                *(float2*)(orow + 8 * NV + col) = v1;
            }
        }
        __syncthreads();
    }
}

// ---------------------------------------------------------------------------
extern "C" void kernel_launch(void* const* d_in, const int* in_sizes, int n_in,
                              void* d_out, int out_size) {
    (void)in_sizes; (void)n_in; (void)out_size;
    const int*   x  = (const int*)d_in[0];
    const float* te = (const float*)d_in[1];
    const float* pe = (const float*)d_in[2];
    const float* Wq = (const float*)d_in[3];  const float* bq = (const float*)d_in[4];
    const float* Wk = (const float*)d_in[5];  const float* bk = (const float*)d_in[6];
    const float* Wv = (const float*)d_in[7];  const float* bv = (const float*)d_in[8];
    const float* Wo = (const float*)d_in[9];  const float* bo = (const float*)d_in[10];
    const float* W1 = (const float*)d_in[11]; const float* b1 = (const float*)d_in[12];
    const float* W2 = (const float*)d_in[13]; const float* b2 = (const float*)d_in[14];
    const float* Wf = (const float*)d_in[15]; const float* bf = (const float*)d_in[16];
    float* out = (float*)d_out;

    k_cvt_all<<<524, 256>>>(Wf, Wo, W1, W2);
    k_qkv<<<dim3(B, H, 3), 128>>>(x, te, pe, Wq, bq, Wk, bk, Wv, bv);

    int attn_smem = A_TOTF * (int)sizeof(float);
    cudaFuncSetAttribute(k_attn, cudaFuncAttributeMaxDynamicSharedMemorySize, attn_smem);
    k_attn<<<dim3(B, H), 256, attn_smem>>>();

    k_ffn_a<<<BT / 16, 256>>>(bo);

    cudaFuncSetAttribute(k_ffn_b, cudaFuncAttributeMaxDynamicSharedMemorySize, FB_TOT);
    k_ffn_b<<<BT / 32, 256, FB_TOT>>>(b1, b2);

    cudaFuncSetAttribute(k_logits_mma, cudaFuncAttributeMaxDynamicSharedMemorySize, S_TOT);
    k_logits_mma<<<NV / 128, 256, S_TOT>>>(bf, out);
}